// round 12
// baseline (speedup 1.0000x reference)
#include <cuda_runtime.h>
#include <cuda_bf16.h>
#include <math.h>

#define B_  20
#define S_  500
#define D_  300
#define H_  600
#define QK_ 128
#define NXS 304
#define ATS 512
#define WOS 304
#define NCAT 1328

typedef __nv_bfloat16 bf16;

// ---------------- scratch (device globals; no allocation) ----------------
__device__ __align__(16) bf16  g_nx_bf[B_*S_*NXS];
__device__ __align__(16) bf16  g_q_bf[B_*S_*QK_];
__device__ __align__(16) bf16  g_k_bf[B_*S_*QK_];
__device__ __align__(16) bf16  g_v_bf[B_*S_*H_];
__device__ __align__(16) bf16  g_gate_bf[B_*S_*H_];
__device__ __align__(16) bf16  g_attn_bf[(size_t)B_*S_*ATS];
__device__ __align__(16) bf16  g_o_bf[B_*S_*H_];
__device__ __align__(16) bf16  g_Wcat[D_*NCAT];
__device__ float g_bcat[NCAT];
__device__ __align__(16) bf16  g_Wout_bf[H_*WOS];
__device__ float g_bias[1024];
__device__ float2 g_rot[S_*16];
__device__ int   g_hist[B_*129];
__device__ unsigned g_gmax[B_];
__device__ unsigned char g_counts[B_*100*120];
__device__ int   g_cmax[B_];
__device__ int   g_hist2[B_*17];

// ---------------- accurate fp32 exp ----------------
__device__ __forceinline__ float my_expf(float x){
    x = fminf(fmaxf(x, -87.0f), 87.0f);
    float t = fmaf(x, 1.4426950408889634f, 12582912.0f);
    float n = t - 12582912.0f;
    float r = fmaf(n, -0.693359375f, x);
    r = fmaf(n, 2.1219444005469058e-4f, r);
    float p = 1.9841269841e-4f;
    p = fmaf(p, r, 1.3888888889e-3f);
    p = fmaf(p, r, 8.3333333333e-3f);
    p = fmaf(p, r, 4.1666666667e-2f);
    p = fmaf(p, r, 1.6666666667e-1f);
    p = fmaf(p, r, 0.5f);
    p = fmaf(p, r, 1.0f);
    p = fmaf(p, r, 1.0f);
    int e = (int)n;
    return p * __int_as_float((e + 127) << 23);
}
__device__ __forceinline__ float silu_f(float v){
    return v * __fdividef(1.0f, 1.0f + my_expf(-v));
}
__device__ __forceinline__ void st_bf2(bf16* p, float lo, float hi){
    __nv_bfloat162 v;
    v.x = __float2bfloat16(lo);
    v.y = __float2bfloat16(hi);
    *reinterpret_cast<__nv_bfloat162*>(p) = v;
}

// ------------- setup -------------
__global__ void setup_kernel(const float* __restrict__ rel_emb,
                             const float* __restrict__ Wh,
                             const float* __restrict__ Wqk,
                             const float* __restrict__ Wout,
                             const float* __restrict__ bh,
                             const float* __restrict__ bqk){
    int i = blockIdx.x * blockDim.x + threadIdx.x;
    if (i < B_*129) g_hist[i] = 0;
    if (i < B_*17)  g_hist2[i] = 0;
    if (i < B_)     { g_gmax[i] = 0u; g_cmax[i] = 0; }
    if (i < 999){
        int n = i - (S_-1);
        int ret = (n < 0) ? 16 : 0;
        int na = n < 0 ? -n : n;
        int bucket;
        if (na < 8) bucket = ret + na;
        else {
            float lnum = (float)log((double)na / 8.0);
            float lden = (float)log(16.0);
            float q = (float)((double)lnum / (double)lden);
            int vil = 8 + (int)(q * 8.0f);
            if (vil > 15) vil = 15;
            bucket = ret + vil;
        }
        g_bias[i] = rel_emb[bucket] * sqrtf(128.0f);
    }
    if (i < S_*16){
        int s = i >> 4, f = i & 15;
        double inv = pow(10000.0, -(double)(2*f)/32.0);
        float fr = (float)s * (float)inv;
        g_rot[i] = make_float2((float)cos((double)fr), (float)sin((double)fr));
    }
    if (i < NCAT) g_bcat[i] = (i < 2*H_) ? bh[i] : bqk[i - 2*H_];
    if (i < D_*NCAT){
        int row = i / NCAT, col = i % NCAT;
        float w = (col < 2*H_) ? Wh[row*(2*H_) + col] : Wqk[row*QK_ + (col - 2*H_)];
        g_Wcat[i] = __float2bfloat16(w);
    }
    if (i < H_*D_){
        int row = i / D_, col = i % D_;
        g_Wout_bf[row*WOS + col] = __float2bfloat16(Wout[i]);
    }
}

// ---------------- LayerNorm, warp-per-row, single-pass ----------------
__global__ __launch_bounds__(128) void ln_kernel(const float* __restrict__ x,
                                                 const float* __restrict__ g,
                                                 const float* __restrict__ b){
    int w = threadIdx.x >> 5, lane = threadIdx.x & 31;
    int bs = blockIdx.x * 4 + w;
    int batch = bs / S_, s = bs % S_;
    const float* xr = x + (size_t)bs * D_;
    float xv[10];
    float sum = 0.f, ss = 0.f;
    #pragma unroll
    for (int j = 0; j < 10; j++){
        int i = j*32 + lane;
        float v = (i < D_) ? xr[i] : 0.f;
        xv[j] = v; sum += v; ss = fmaf(v, v, ss);
    }
    #pragma unroll
    for (int o = 16; o; o >>= 1){
        sum += __shfl_xor_sync(0xffffffffu, sum, o);
        ss  += __shfl_xor_sync(0xffffffffu, ss,  o);
    }
    float mean = sum * (1.0f / D_);
    float var  = ss * (1.0f / D_) - mean*mean;
    float inv  = rsqrtf(var + 1e-5f);
    size_t selfRow = (size_t)bs * NXS;
    size_t nextRow = ((size_t)batch*S_ + s + 1) * NXS;
    #pragma unroll
    for (int j = 0; j < 10; j++){
        int i = j*32 + lane;
        if (i >= D_) break;
        float val = (xv[j]-mean)*inv*g[i] + b[i];
        if (i < D_/2){
            if (s+1 < S_) g_nx_bf[nextRow + i] = __float2bfloat16(val);
        } else {
            g_nx_bf[selfRow + i] = __float2bfloat16(val);
        }
    }
    if (s == 0){
        #pragma unroll
        for (int j = 0; j < 5; j++){
            int i = j*32 + lane;
            if (i < D_/2) g_nx_bf[selfRow + i] = __float2bfloat16(0.f);
        }
    }
}

// ===== bf16 mma.sync GEMM: BM=128, BN templated, 3-stage cp.async.cg =====
#define BM 128
#define BK 32
#define ASTR 40
#define A_ST (BM*ASTR)
#define NSTG 3

__device__ __forceinline__ void mma16816(float c[4], const unsigned a[4], const unsigned b[2]){
    asm volatile("mma.sync.aligned.m16n8k16.row.col.f32.bf16.bf16.f32 "
                 "{%0,%1,%2,%3}, {%4,%5,%6,%7}, {%8,%9}, {%0,%1,%2,%3};"
                 : "+f"(c[0]), "+f"(c[1]), "+f"(c[2]), "+f"(c[3])
                 : "r"(a[0]), "r"(a[1]), "r"(a[2]), "r"(a[3]), "r"(b[0]), "r"(b[1]));
}
__device__ __forceinline__ void cp16(unsigned dst, const void* src, int bytes){
    asm volatile("cp.async.cg.shared.global [%0], [%1], 16, %2;" :: "r"(dst), "l"(src), "r"(bytes));
}
__device__ __forceinline__ void cp_commit(){ asm volatile("cp.async.commit_group;"); }
__device__ __forceinline__ void cp_wait1(){ asm volatile("cp.async.wait_group 1;"); }
__device__ __forceinline__ int clampb(int rem){ return rem < 0 ? 0 : (rem > 16 ? 16 : rem); }

template<int BN_, bool TRANS_B, class Epi>
__global__ __launch_bounds__(256) void gemm_bf(const bf16* __restrict__ A,
        const bf16* __restrict__ Bm, int M, int N, int K, int lda, int ldb,
        long sA, long sB, Epi epi)
{
    constexpr int WN_CNT = BN_/32;
    constexpr int WM_CNT = 8/WN_CNT;
    constexpr int WROWS  = BM/WM_CNT;
    constexpr int MI     = WROWS/16;
    constexpr int BSTR   = TRANS_B ? ASTR : (BN_ + 8);
    constexpr int B_ST_L = TRANS_B ? BN_*ASTR : BK*BSTR;

    __shared__ bf16 smA[NSTG][A_ST];
    __shared__ bf16 smB[NSTG][B_ST_L];

    int bz = blockIdx.z;
    A  += (size_t)bz * sA;
    Bm += (size_t)bz * sB;
    int row0 = blockIdx.y*BM, col0 = blockIdx.x*BN_;
    int tid = threadIdx.x, warp = tid>>5, lane = tid&31;
    int wm = warp / WN_CNT, wn = warp % WN_CNT;
    int gr8 = lane>>2, t4 = lane&3;

    unsigned aS = (unsigned)__cvta_generic_to_shared(&smA[0][0]);
    unsigned bS = (unsigned)__cvta_generic_to_shared(&smB[0][0]);

    int ar = tid>>2;
    int ak = (tid&3)*8;
    bool vA0 = (row0 + ar)      < M;
    bool vA1 = (row0 + ar + 64) < M;
    const bf16* pA0 = A + (size_t)(row0 + ar)      * lda + ak;
    const bf16* pA1 = A + (size_t)(row0 + ar + 64) * lda + ak;
    unsigned dA0 = aS + (unsigned)((ar*ASTR + ak)*2);
    unsigned dA1 = dA0 + (unsigned)(64*ASTR*2);

    bool vB0 = true, vB1 = true;
    const bf16* pB0 = Bm; const bf16* pB1 = Bm;
    unsigned dB0 = bS, dB1 = bS;
    int constNB = 0;
    int bk8 = 0, brow = 0;
    if (TRANS_B){
        if (BN_ == 128){
            brow = tid>>2; bk8 = (tid&3)*8;
            vB0 = (col0 + brow)      < N;
            vB1 = (col0 + brow + 64) < N;
            pB0 = Bm + (size_t)(col0 + brow)      * ldb + bk8;
            pB1 = Bm + (size_t)(col0 + brow + 64) * ldb + bk8;
            dB0 = bS + (unsigned)((brow*ASTR + bk8)*2);
            dB1 = dB0 + (unsigned)(64*ASTR*2);
        } else {
            brow = tid>>2; bk8 = (tid&3)*8;
            vB0 = (col0 + brow) < N;
            pB0 = Bm + (size_t)(col0 + brow) * ldb + bk8;
            dB0 = bS + (unsigned)((brow*ASTR + bk8)*2);
        }
    } else {
        if (BN_ == 128){
            brow = tid>>4;
            int bc8 = (tid&15)*8;
            int gn = col0 + bc8;
            constNB = clampb((N - gn)*2);
            pB0 = Bm + (size_t)brow * ldb + gn;
            pB1 = pB0 + (size_t)16 * ldb;
            dB0 = bS + (unsigned)((brow*BSTR + bc8)*2);
            dB1 = dB0 + (unsigned)(16*BSTR*2);
        } else {
            brow = tid>>3;
            int bc8 = (tid&7)*8;
            int gn = col0 + bc8;
            constNB = clampb((N - gn)*2);
            pB0 = Bm + (size_t)brow * ldb + gn;
            dB0 = bS + (unsigned)((brow*BSTR + bc8)*2);
        }
    }

    auto load_stage = [&](unsigned soA, unsigned soB, int kk){
        int bytes0 = vA0 ? clampb((K - (kk + ak))*2) : 0;
        int bytes1 = vA1 ? clampb((K - (kk + ak))*2) : 0;
        cp16(dA0 + soA, bytes0 ? (const void*)pA0 : (const void*)A, bytes0);
        cp16(dA1 + soA, bytes1 ? (const void*)pA1 : (const void*)A, bytes1);
        pA0 += BK; pA1 += BK;
        if (TRANS_B){
            int kb = clampb((K - (kk + bk8))*2);
            int b0 = vB0 ? kb : 0;
            cp16(dB0 + soB, b0 ? (const void*)pB0 : (const void*)Bm, b0);
            pB0 += BK;
            if (BN_ == 128){
                int b1 = vB1 ? kb : 0;
                cp16(dB1 + soB, b1 ? (const void*)pB1 : (const void*)Bm, b1);
                pB1 += BK;
            }
        } else {
            int b0 = ((kk + brow) < K) ? constNB : 0;
            cp16(dB0 + soB, b0 ? (const void*)pB0 : (const void*)Bm, b0);
            pB0 += (size_t)BK * ldb;
            if (BN_ == 128){
                int b1 = ((kk + brow + 16) < K) ? constNB : 0;
                cp16(dB1 + soB, b1 ? (const void*)pB1 : (const void*)Bm, b1);
                pB1 += (size_t)BK * ldb;
            }
        }
    };

    unsigned aAddrBase = aS + (unsigned)(((wm*WROWS + (lane&15))*ASTR + (lane>>4)*8)*2);
    unsigned bAddrBase;
    {
        int m = lane>>3, i = lane&7;
        if (TRANS_B){
            int rowoff = i + ((m>>1)<<3);
            int kcoff  = (m&1)<<3;
            bAddrBase = bS + (unsigned)(((wn*32 + rowoff)*ASTR + kcoff)*2);
        } else {
            int krow = i + ((m&1)<<3);
            int ncoff = (m>>1)<<3;
            bAddrBase = bS + (unsigned)((krow*BSTR + wn*32 + ncoff)*2);
        }
    }

    float acc[MI][4][4] = {};

    int nk = (K + BK - 1)/BK;
    load_stage(0, 0, 0);                 cp_commit();
    load_stage(A_ST*2, B_ST_L*2, BK);    cp_commit();

    unsigned poA = 2*A_ST*2, poB = 2*B_ST_L*2;
    unsigned coA = 0,        coB = 0;

    for (int it = 0; it < nk; it++){
        cp_wait1();
        __syncthreads();
        if (it + 2 < nk) load_stage(poA, poB, (it+2)*BK);
        cp_commit();
        poA += A_ST*2;   if (poA == NSTG*A_ST*2)   poA = 0;
        poB += B_ST_L*2; if (poB == NSTG*B_ST_L*2) poB = 0;

        unsigned aAddr = aAddrBase + coA;
        unsigned bAddr = bAddrBase + coB;
        #pragma unroll
        for (int ks = 0; ks < 2; ks++){
            unsigned ra[MI][4];
            #pragma unroll
            for (int mi = 0; mi < MI; mi++){
                unsigned ad = aAddr + (unsigned)((mi*16*ASTR + ks*16)*2);
                asm volatile("ldmatrix.sync.aligned.m8n8.x4.shared.b16 {%0,%1,%2,%3}, [%4];"
                    : "=r"(ra[mi][0]),"=r"(ra[mi][1]),"=r"(ra[mi][2]),"=r"(ra[mi][3]) : "r"(ad));
            }
            unsigned rb[4][2];
            #pragma unroll
            for (int h = 0; h < 2; h++){
                unsigned r0,r1,r2,r3;
                if (TRANS_B){
                    unsigned bd = bAddr + (unsigned)((h*16*ASTR + ks*16)*2);
                    asm volatile("ldmatrix.sync.aligned.m8n8.x4.shared.b16 {%0,%1,%2,%3}, [%4];"
                        : "=r"(r0),"=r"(r1),"=r"(r2),"=r"(r3) : "r"(bd));
                } else {
                    unsigned bd = bAddr + (unsigned)((ks*16*BSTR + h*16)*2);
                    asm volatile("ldmatrix.sync.aligned.m8n8.x4.trans.shared.b16 {%0,%1,%2,%3}, [%4];"
                        : "=r"(r0),"=r"(r1),"=r"(r2),"=r"(r3) : "r"(bd));
                }
                rb[h*2][0]=r0; rb[h*2][1]=r1; rb[h*2+1][0]=r2; rb[h*2+1][1]=r3;
            }
            #pragma unroll
            for (int mi = 0; mi < MI; mi++)
                #pragma unroll
                for (int ni = 0; ni < 4; ni++)
                    mma16816(acc[mi][ni], ra[mi], rb[ni]);
        }
        coA += A_ST*2;   if (coA == NSTG*A_ST*2)   coA = 0;
        coB += B_ST_L*2; if (coB == NSTG*B_ST_L*2) coB = 0;
    }

    #pragma unroll
    for (int mi = 0; mi < MI; mi++)
        #pragma unroll
        for (int ni = 0; ni < 4; ni++){
            int c = col0 + wn*32 + ni*8 + t4*2;
            int nv = (c + 1 < N) ? 2 : (c < N ? 1 : 0);
            if (nv){
                int r = row0 + wm*WROWS + mi*16 + gr8;
                if (r < M)     epi(bz, r,     c, acc[mi][ni][0], acc[mi][ni][1], nv);
                if (r + 8 < M) epi(bz, r + 8, c, acc[mi][ni][2], acc[mi][ni][3], nv);
            }
        }
    epi.finalize();
}

// ---------------- epilogues ----------------
struct EpiCat {
    const float* gamma; const float* beta;
    int batchA = -1, batchB = -1;
    unsigned maxA = 0, maxB = 0;
    // track gate value (bf16-rounded, matching downstream consumers)
    __device__ __forceinline__ void track(int batch, float gf){
        float gv = __bfloat162float(__float2bfloat16(gf));
        unsigned u = __float_as_uint(gv);
        u = (u & 0x80000000u) ? ~u : (u | 0x80000000u);
        if (batch == batchA){ if (u > maxA) maxA = u; }
        else if (batch == batchB){ if (u > maxB) maxB = u; }
        else if (batchA < 0){ batchA = batch; maxA = u; }
        else { batchB = batch; maxB = u; }
        float a = fabsf(gv);
        if (a >= 1.0f){   // hist[0] is never read by trim; only bins >= 1 matter
            int bin = (int)floorf(a); if (bin > 128) bin = 128;
            atomicAdd(&g_hist[batch*129 + bin], 1);
        }
    }
    __device__ void operator()(int, int r, int c, float a0, float a1, int nv) {
        if (c < 2*H_){
            float s0 = silu_f(a0 + g_bcat[c]);
            float s1 = silu_f(a1 + g_bcat[c+1]);
            if (c < H_)  st_bf2(&g_v_bf[(size_t)r*H_ + c], s0, s1);
            else {
                st_bf2(&g_gate_bf[(size_t)r*H_ + c - H_], s0, s1);
                int batch = r / S_;
                track(batch, s0);
                track(batch, s1);
            }
        } else {
            int cq = c - 2*H_;
            int s = r % S_;
            float s0 = silu_f(a0 + g_bcat[c]);
            float s1 = silu_f(a1 + g_bcat[c+1]);
            float q0 = fmaf(s0, gamma[cq],        beta[cq]);
            float q1 = fmaf(s1, gamma[cq+1],      beta[cq+1]);
            float k0 = fmaf(s0, gamma[QK_+cq],    beta[QK_+cq]);
            float k1 = fmaf(s1, gamma[QK_+cq+1],  beta[QK_+cq+1]);
            if (cq < 32){
                float2 cs = g_rot[s*16 + (cq>>1)];
                float q0n = q0*cs.x - q1*cs.y, q1n = q1*cs.x + q0*cs.y;
                float k0n = k0*cs.x - k1*cs.y, k1n = k1*cs.x + k0*cs.y;
                q0=q0n; q1=q1n; k0=k0n; k1=k1n;
            }
            size_t base = (size_t)r*QK_;
            st_bf2(&g_q_bf[base+cq], q0, q1);
            st_bf2(&g_k_bf[base+cq], k0, k1);
        }
    }
    __device__ void finalize(){
        #pragma unroll
        for (int sl = 0; sl < 2; sl++){
            int batch = sl ? batchB : batchA;
            unsigned mx = sl ? maxB : maxA;
            unsigned m = __match_any_sync(0xffffffffu, batch);
            unsigned tot = __reduce_max_sync(m, mx);
            int leader = __ffs(m) - 1;
            if ((int)(threadIdx.x & 31) == leader && batch >= 0)
                atomicMax(&g_gmax[batch], tot);
        }
    }
};
struct EpiScores {
    const float* mask2;
    __device__ void operator()(int bz, int r, int c, float a0, float a1, int nv) {
        size_t rowb = ((size_t)bz*S_ + r)*ATS;
        if (nv == 2){
            float2 mk = *reinterpret_cast<const float2*>(&mask2[r*S_ + c]);
            float v0 = a0 + g_bias[r - c + (S_-1)];
            float v1 = a1 + g_bias[r - c - 1 + (S_-1)];
            float t0 = fmaxf(v0 * (1.0f/S_), 0.f);
            float t1 = fmaxf(v1 * (1.0f/S_), 0.f);
            st_bf2(&g_attn_bf[rowb + c], t0*t0*mk.x, t1*t1*mk.y);
        } else {
            float v0 = a0 + g_bias[r - c + (S_-1)];
            float t0 = fmaxf(v0 * (1.0f/S_), 0.f);
            g_attn_bf[rowb + c] = __float2bfloat16(t0*t0*mask2[r*S_ + c]);
        }
    }
    __device__ void finalize(){}
};
struct EpiOut {
    int t2c = -1;
    __device__ __forceinline__ int get_t2(int bz){
        if (t2c < 0){
            int cm = g_cmax[bz];
            int cnt = 0, best = -1;
            #pragma unroll
            for (int t = 16; t >= 1; t--){
                cnt += g_hist2[bz*17 + t];
                if (t <= cm && cnt > 3600 && t > best) best = t;
            }
            t2c = (best >= 0) ? best : cm;
        }
        return t2c;
    }
    __device__ __forceinline__ float gm(int bz, int r, int c, int t2){
        int rr = r % 5, cc = c % 5;
        if (rr == 4 || cc == 4) return 0.0f;
        int cnt = g_counts[bz*12000 + (r/5)*120 + (c/5)];
        return (cnt >= t2) ? 1.0f : 0.25f;
    }
    __device__ void operator()(int bz, int r, int c, float a0, float a1, int nv) {
        int t2 = get_t2(bz);
        size_t idx = ((size_t)bz*S_ + r)*H_ + c;
        if (nv == 2){
            __nv_bfloat162 gt = *reinterpret_cast<const __nv_bfloat162*>(&g_gate_bf[idx]);
            st_bf2(&g_o_bf[idx],
                   gm(bz,r,c,t2)   * a0 * __bfloat162float(gt.x),
                   gm(bz,r,c+1,t2) * a1 * __bfloat162float(gt.y));
        } else {
            g_o_bf[idx] = __float2bfloat16(gm(bz,r,c,t2) * a0 * __bfloat162float(g_gate_bf[idx]));
        }
    }
    __device__ void finalize(){}
};
struct EpiFinal {
    const float* bout; const float* x; float* out;
    __device__ void operator()(int, int r, int c, float a0, float a1, int nv) {
        size_t idx = (size_t)r*D_ + c;
        if (nv == 2){
            float2 xv = *reinterpret_cast<const float2*>(&x[idx]);
            *reinterpret_cast<float2*>(&out[idx]) =
                make_float2(a0 + bout[c] + xv.x, a1 + bout[c+1] + xv.y);
        } else {
            out[idx] = a0 + bout[c] + x[idx];
        }
    }
    __device__ void finalize(){}
};

// ---------------- counts (reads bf16 gate; trim inlined from g_hist/g_gmax) ----------------
__global__ __launch_bounds__(256) void counts_kernel(){
    int b = blockIdx.y;
    __shared__ int shist[129];
    __shared__ int strim;
    __shared__ int sh2[17];
    __shared__ int scmax;
    int tid = threadIdx.x;
    if (tid < 129) shist[tid] = g_hist[b*129 + tid];
    if (tid < 17)  sh2[tid] = 0;
    if (tid == 0)  scmax = 0;
    __syncthreads();
    if (tid == 0){
        unsigned u = g_gmax[b];
        u = (u & 0x80000000u) ? (u & 0x7FFFFFFFu) : ~u;
        int gmax = (int)floorf(__uint_as_float(u));
        int cnt = 0, best = 0;
        for (int t = 128; t >= 1; t--){
            cnt += shist[t];
            if (t <= gmax && cnt > 90000 && t > best) best = t;
        }
        strim = best < 1 ? 1 : best;
    }
    __syncthreads();
    int idx = blockIdx.x*256 + tid;
    if (idx < 12000){
        int i = idx / 120, j = idx % 120;
        float thr = (float)strim;
        const bf16* gb = g_gate_bf + (size_t)b*S_*H_;
        int cnt = 0;
        #pragma unroll
        for (int r = 0; r < 4; r++)
            #pragma unroll
            for (int c = 0; c < 4; c++)
                cnt += (fabsf(__bfloat162float(gb[(i*5+r)*H_ + j*5+c])) >= thr);
        g_counts[b*12000 + idx] = (unsigned char)cnt;
        atomicMax(&scmax, cnt);
        atomicAdd(&sh2[cnt], 1);
    }
    __syncthreads();
    if (tid < 17 && sh2[tid]) atomicAdd(&g_hist2[b*17 + tid], sh2[tid]);
    if (tid == 0) atomicMax(&g_cmax[b], scmax);
}

// ---------------- launch ----------------
extern "C" void kernel_launch(void* const* d_in, const int* in_sizes, int n_in,
                              void* d_out, int out_size){
    (void)in_sizes; (void)n_in; (void)out_size;
    const float* x       = (const float*)d_in[0];
    const float* mask2   = (const float*)d_in[1];
    const float* ln_g    = (const float*)d_in[2];
    const float* ln_b    = (const float*)d_in[3];
    const float* Wh      = (const float*)d_in[4];
    const float* bh      = (const float*)d_in[5];
    const float* Wqk     = (const float*)d_in[6];
    const float* bqk     = (const float*)d_in[7];
    const float* gamma   = (const float*)d_in[8];
    const float* beta    = (const float*)d_in[9];
    const float* rel_emb = (const float*)d_in[10];
    const float* Wout    = (const float*)d_in[11];
    const float* bout    = (const float*)d_in[12];
    float* out = (float*)d_out;

    bf16 *nx, *q, *k, *v, *attn, *o, *wcat, *wout;
    cudaGetSymbolAddress((void**)&nx,   g_nx_bf);
    cudaGetSymbolAddress((void**)&q,    g_q_bf);
    cudaGetSymbolAddress((void**)&k,    g_k_bf);
    cudaGetSymbolAddress((void**)&v,    g_v_bf);
    cudaGetSymbolAddress((void**)&attn, g_attn_bf);
    cudaGetSymbolAddress((void**)&o,    g_o_bf);
    cudaGetSymbolAddress((void**)&wcat, g_Wcat);
    cudaGetSymbolAddress((void**)&wout, g_Wout_bf);

    const int M = B_*S_;   // 10000

    setup_kernel<<<(D_*NCAT + 255)/256, 256>>>(rel_emb, Wh, Wqk, Wout, bh, bqk);
    ln_kernel<<<M/4, 128>>>(x, ln_g, ln_b);

    // combined: [h | qk] = silu(nx @ Wcat + bcat); gamma/beta+rotary fused on qk region;
    // gate histogram (bins>=1) + per-batch max fused into the epilogue
    gemm_bf<64,false><<<dim3((NCAT+63)/64, (M+BM-1)/BM, 1), 256>>>(
        nx, wcat, M, NCAT, D_, NXS, NCAT, 0L, 0L, EpiCat{gamma, beta});

    // attn scores (batched NT)
    gemm_bf<64,true><<<dim3((S_+63)/64, (S_+BM-1)/BM, B_), 256>>>(
        q, k, S_, S_, QK_, QK_, QK_, (long)S_*QK_, (long)S_*QK_, EpiScores{mask2});

    counts_kernel<<<dim3(47, B_), 256>>>();

    // o = gm * (attn @ v) * gate
    gemm_bf<64,false><<<dim3((H_+63)/64, (S_+BM-1)/BM, B_), 256>>>(
        attn, v, S_, H_, S_, ATS, H_, (long)S_*ATS, (long)S_*H_, EpiOut{});

    // out = o @ Wout + bout + x
    gemm_bf<64,false><<<dim3((D_+63)/64, (M+BM-1)/BM, 1), 256>>>(
        o, wout, M, D_, H_, H_, WOS, 0L, 0L, EpiFinal{bout, x, out});
}

// round 13
// speedup vs baseline: 1.1242x; 1.1242x over previous
#include <cuda_runtime.h>
#include <cuda_bf16.h>
#include <math.h>

#define B_  20
#define S_  500
#define D_  300
#define H_  600
#define QK_ 128
#define NXS 304
#define ATS 512
#define WOS 304
#define NCAT 1328
#define SETUP_BLOCKS ((D_*NCAT + 255)/256)   // 1557
#define LN_BLOCKS (B_*S_/8)                  // 1250

typedef __nv_bfloat16 bf16;

// ---------------- scratch (device globals; no allocation) ----------------
__device__ __align__(16) bf16  g_nx_bf[B_*S_*NXS];
__device__ __align__(16) bf16  g_q_bf[B_*S_*QK_];
__device__ __align__(16) bf16  g_k_bf[B_*S_*QK_];
__device__ __align__(16) bf16  g_v_bf[B_*S_*H_];
__device__ __align__(16) bf16  g_gate_bf[B_*S_*H_];
__device__ __align__(16) bf16  g_attn_bf[(size_t)B_*S_*ATS];
__device__ __align__(16) bf16  g_o_bf[B_*S_*H_];
__device__ __align__(16) bf16  g_Wcat[D_*NCAT];
__device__ float g_bcat[NCAT];
__device__ __align__(16) bf16  g_Wout_bf[H_*WOS];
__device__ float g_bias[1024];
__device__ float2 g_rot[S_*16];
__device__ int   g_hist[B_*129];
__device__ unsigned g_gmax[B_];
__device__ unsigned char g_counts[B_*100*120];
__device__ int   g_cmax[B_];
__device__ int   g_hist2[B_*17];

// ---------------- accurate fp32 exp ----------------
__device__ __forceinline__ float my_expf(float x){
    x = fminf(fmaxf(x, -87.0f), 87.0f);
    float t = fmaf(x, 1.4426950408889634f, 12582912.0f);
    float n = t - 12582912.0f;
    float r = fmaf(n, -0.693359375f, x);
    r = fmaf(n, 2.1219444005469058e-4f, r);
    float p = 1.9841269841e-4f;
    p = fmaf(p, r, 1.3888888889e-3f);
    p = fmaf(p, r, 8.3333333333e-3f);
    p = fmaf(p, r, 4.1666666667e-2f);
    p = fmaf(p, r, 1.6666666667e-1f);
    p = fmaf(p, r, 0.5f);
    p = fmaf(p, r, 1.0f);
    p = fmaf(p, r, 1.0f);
    int e = (int)n;
    return p * __int_as_float((e + 127) << 23);
}
__device__ __forceinline__ float silu_f(float v){
    return v * __fdividef(1.0f, 1.0f + my_expf(-v));
}
__device__ __forceinline__ void st_bf2(bf16* p, float lo, float hi){
    __nv_bfloat162 v;
    v.x = __float2bfloat16(lo);
    v.y = __float2bfloat16(hi);
    *reinterpret_cast<__nv_bfloat162*>(p) = v;
}

// ------------- merged setup + LayerNorm (independent work, one launch) -------------
__global__ __launch_bounds__(256) void setup_ln_kernel(
        const float* __restrict__ rel_emb,
        const float* __restrict__ Wh,
        const float* __restrict__ Wqk,
        const float* __restrict__ Wout,
        const float* __restrict__ bh,
        const float* __restrict__ bqk,
        const float* __restrict__ x,
        const float* __restrict__ lg,
        const float* __restrict__ lb){
    if (blockIdx.x < SETUP_BLOCKS){
        int i = blockIdx.x * 256 + threadIdx.x;
        if (i < B_*129) g_hist[i] = 0;
        if (i < B_*17)  g_hist2[i] = 0;
        if (i < B_)     { g_gmax[i] = 0u; g_cmax[i] = 0; }
        if (i < 999){
            int n = i - (S_-1);
            int ret = (n < 0) ? 16 : 0;
            int na = n < 0 ? -n : n;
            int bucket;
            if (na < 8) bucket = ret + na;
            else {
                float lnum = (float)log((double)na / 8.0);
                float lden = (float)log(16.0);
                float q = (float)((double)lnum / (double)lden);
                int vil = 8 + (int)(q * 8.0f);
                if (vil > 15) vil = 15;
                bucket = ret + vil;
            }
            g_bias[i] = rel_emb[bucket] * sqrtf(128.0f);
        }
        if (i < S_*16){
            int s = i >> 4, f = i & 15;
            double inv = pow(10000.0, -(double)(2*f)/32.0);
            float fr = (float)s * (float)inv;
            g_rot[i] = make_float2((float)cos((double)fr), (float)sin((double)fr));
        }
        if (i < NCAT) g_bcat[i] = (i < 2*H_) ? bh[i] : bqk[i - 2*H_];
        if (i < D_*NCAT){
            int row = i / NCAT, col = i % NCAT;
            float w = (col < 2*H_) ? Wh[row*(2*H_) + col] : Wqk[row*QK_ + (col - 2*H_)];
            g_Wcat[i] = __float2bfloat16(w);
        }
        if (i < H_*D_){
            int row = i / D_, col = i % D_;
            g_Wout_bf[row*WOS + col] = __float2bfloat16(Wout[i]);
        }
    } else {
        // LayerNorm: warp-per-row, 8 rows per block
        int w = threadIdx.x >> 5, lane = threadIdx.x & 31;
        int bs = (blockIdx.x - SETUP_BLOCKS) * 8 + w;
        int batch = bs / S_, s = bs % S_;
        const float* xr = x + (size_t)bs * D_;
        float xv[10];
        float sum = 0.f, ss = 0.f;
        #pragma unroll
        for (int j = 0; j < 10; j++){
            int i = j*32 + lane;
            float v = (i < D_) ? xr[i] : 0.f;
            xv[j] = v; sum += v; ss = fmaf(v, v, ss);
        }
        #pragma unroll
        for (int o = 16; o; o >>= 1){
            sum += __shfl_xor_sync(0xffffffffu, sum, o);
            ss  += __shfl_xor_sync(0xffffffffu, ss,  o);
        }
        float mean = sum * (1.0f / D_);
        float var  = ss * (1.0f / D_) - mean*mean;
        float inv  = rsqrtf(var + 1e-5f);
        size_t selfRow = (size_t)bs * NXS;
        size_t nextRow = ((size_t)batch*S_ + s + 1) * NXS;
        #pragma unroll
        for (int j = 0; j < 10; j++){
            int i = j*32 + lane;
            if (i >= D_) break;
            float val = (xv[j]-mean)*inv*lg[i] + lb[i];
            if (i < D_/2){
                if (s+1 < S_) g_nx_bf[nextRow + i] = __float2bfloat16(val);
            } else {
                g_nx_bf[selfRow + i] = __float2bfloat16(val);
            }
        }
        if (s == 0){
            #pragma unroll
            for (int j = 0; j < 5; j++){
                int i = j*32 + lane;
                if (i < D_/2) g_nx_bf[selfRow + i] = __float2bfloat16(0.f);
            }
        }
    }
}

// ===== bf16 mma.sync GEMM: BM=128, BN templated, 3-stage cp.async.cg =====
#define BM 128
#define BK 32
#define ASTR 40
#define A_ST (BM*ASTR)
#define NSTG 3

__device__ __forceinline__ void mma16816(float c[4], const unsigned a[4], const unsigned b[2]){
    asm volatile("mma.sync.aligned.m16n8k16.row.col.f32.bf16.bf16.f32 "
                 "{%0,%1,%2,%3}, {%4,%5,%6,%7}, {%8,%9}, {%0,%1,%2,%3};"
                 : "+f"(c[0]), "+f"(c[1]), "+f"(c[2]), "+f"(c[3])
                 : "r"(a[0]), "r"(a[1]), "r"(a[2]), "r"(a[3]), "r"(b[0]), "r"(b[1]));
}
__device__ __forceinline__ void cp16(unsigned dst, const void* src, int bytes){
    asm volatile("cp.async.cg.shared.global [%0], [%1], 16, %2;" :: "r"(dst), "l"(src), "r"(bytes));
}
__device__ __forceinline__ void cp_commit(){ asm volatile("cp.async.commit_group;"); }
__device__ __forceinline__ void cp_wait1(){ asm volatile("cp.async.wait_group 1;"); }
__device__ __forceinline__ int clampb(int rem){ return rem < 0 ? 0 : (rem > 16 ? 16 : rem); }

template<int BN_, bool TRANS_B, class Epi>
__global__ __launch_bounds__(256) void gemm_bf(const bf16* __restrict__ A,
        const bf16* __restrict__ Bm, int M, int N, int K, int lda, int ldb,
        long sA, long sB, Epi epi)
{
    constexpr int WN_CNT = BN_/32;
    constexpr int WM_CNT = 8/WN_CNT;
    constexpr int WROWS  = BM/WM_CNT;
    constexpr int MI     = WROWS/16;
    constexpr int BSTR   = TRANS_B ? ASTR : (BN_ + 8);
    constexpr int B_ST_L = TRANS_B ? BN_*ASTR : BK*BSTR;

    __shared__ bf16 smA[NSTG][A_ST];
    __shared__ bf16 smB[NSTG][B_ST_L];

    int bz = blockIdx.z;
    A  += (size_t)bz * sA;
    Bm += (size_t)bz * sB;
    int row0 = blockIdx.y*BM, col0 = blockIdx.x*BN_;
    int tid = threadIdx.x, warp = tid>>5, lane = tid&31;
    int wm = warp / WN_CNT, wn = warp % WN_CNT;
    int gr8 = lane>>2, t4 = lane&3;

    unsigned aS = (unsigned)__cvta_generic_to_shared(&smA[0][0]);
    unsigned bS = (unsigned)__cvta_generic_to_shared(&smB[0][0]);

    int ar = tid>>2;
    int ak = (tid&3)*8;
    bool vA0 = (row0 + ar)      < M;
    bool vA1 = (row0 + ar + 64) < M;
    const bf16* pA0 = A + (size_t)(row0 + ar)      * lda + ak;
    const bf16* pA1 = A + (size_t)(row0 + ar + 64) * lda + ak;
    unsigned dA0 = aS + (unsigned)((ar*ASTR + ak)*2);
    unsigned dA1 = dA0 + (unsigned)(64*ASTR*2);

    bool vB0 = true, vB1 = true;
    const bf16* pB0 = Bm; const bf16* pB1 = Bm;
    unsigned dB0 = bS, dB1 = bS;
    int constNB = 0;
    int bk8 = 0, brow = 0;
    if (TRANS_B){
        if (BN_ == 128){
            brow = tid>>2; bk8 = (tid&3)*8;
            vB0 = (col0 + brow)      < N;
            vB1 = (col0 + brow + 64) < N;
            pB0 = Bm + (size_t)(col0 + brow)      * ldb + bk8;
            pB1 = Bm + (size_t)(col0 + brow + 64) * ldb + bk8;
            dB0 = bS + (unsigned)((brow*ASTR + bk8)*2);
            dB1 = dB0 + (unsigned)(64*ASTR*2);
        } else {
            brow = tid>>2; bk8 = (tid&3)*8;
            vB0 = (col0 + brow) < N;
            pB0 = Bm + (size_t)(col0 + brow) * ldb + bk8;
            dB0 = bS + (unsigned)((brow*ASTR + bk8)*2);
        }
    } else {
        if (BN_ == 128){
            brow = tid>>4;
            int bc8 = (tid&15)*8;
            int gn = col0 + bc8;
            constNB = clampb((N - gn)*2);
            pB0 = Bm + (size_t)brow * ldb + gn;
            pB1 = pB0 + (size_t)16 * ldb;
            dB0 = bS + (unsigned)((brow*BSTR + bc8)*2);
            dB1 = dB0 + (unsigned)(16*BSTR*2);
        } else {
            brow = tid>>3;
            int bc8 = (tid&7)*8;
            int gn = col0 + bc8;
            constNB = clampb((N - gn)*2);
            pB0 = Bm + (size_t)brow * ldb + gn;
            dB0 = bS + (unsigned)((brow*BSTR + bc8)*2);
        }
    }

    auto load_stage = [&](unsigned soA, unsigned soB, int kk){
        int bytes0 = vA0 ? clampb((K - (kk + ak))*2) : 0;
        int bytes1 = vA1 ? clampb((K - (kk + ak))*2) : 0;
        cp16(dA0 + soA, bytes0 ? (const void*)pA0 : (const void*)A, bytes0);
        cp16(dA1 + soA, bytes1 ? (const void*)pA1 : (const void*)A, bytes1);
        pA0 += BK; pA1 += BK;
        if (TRANS_B){
            int kb = clampb((K - (kk + bk8))*2);
            int b0 = vB0 ? kb : 0;
            cp16(dB0 + soB, b0 ? (const void*)pB0 : (const void*)Bm, b0);
            pB0 += BK;
            if (BN_ == 128){
                int b1 = vB1 ? kb : 0;
                cp16(dB1 + soB, b1 ? (const void*)pB1 : (const void*)Bm, b1);
                pB1 += BK;
            }
        } else {
            int b0 = ((kk + brow) < K) ? constNB : 0;
            cp16(dB0 + soB, b0 ? (const void*)pB0 : (const void*)Bm, b0);
            pB0 += (size_t)BK * ldb;
            if (BN_ == 128){
                int b1 = ((kk + brow + 16) < K) ? constNB : 0;
                cp16(dB1 + soB, b1 ? (const void*)pB1 : (const void*)Bm, b1);
                pB1 += (size_t)BK * ldb;
            }
        }
    };

    unsigned aAddrBase = aS + (unsigned)(((wm*WROWS + (lane&15))*ASTR + (lane>>4)*8)*2);
    unsigned bAddrBase;
    {
        int m = lane>>3, i = lane&7;
        if (TRANS_B){
            int rowoff = i + ((m>>1)<<3);
            int kcoff  = (m&1)<<3;
            bAddrBase = bS + (unsigned)(((wn*32 + rowoff)*ASTR + kcoff)*2);
        } else {
            int krow = i + ((m&1)<<3);
            int ncoff = (m>>1)<<3;
            bAddrBase = bS + (unsigned)((krow*BSTR + wn*32 + ncoff)*2);
        }
    }

    float acc[MI][4][4] = {};

    int nk = (K + BK - 1)/BK;
    load_stage(0, 0, 0);                 cp_commit();
    load_stage(A_ST*2, B_ST_L*2, BK);    cp_commit();

    unsigned poA = 2*A_ST*2, poB = 2*B_ST_L*2;
    unsigned coA = 0,        coB = 0;

    for (int it = 0; it < nk; it++){
        cp_wait1();
        __syncthreads();
        if (it + 2 < nk) load_stage(poA, poB, (it+2)*BK);
        cp_commit();
        poA += A_ST*2;   if (poA == NSTG*A_ST*2)   poA = 0;
        poB += B_ST_L*2; if (poB == NSTG*B_ST_L*2) poB = 0;

        unsigned aAddr = aAddrBase + coA;
        unsigned bAddr = bAddrBase + coB;
        #pragma unroll
        for (int ks = 0; ks < 2; ks++){
            unsigned ra[MI][4];
            #pragma unroll
            for (int mi = 0; mi < MI; mi++){
                unsigned ad = aAddr + (unsigned)((mi*16*ASTR + ks*16)*2);
                asm volatile("ldmatrix.sync.aligned.m8n8.x4.shared.b16 {%0,%1,%2,%3}, [%4];"
                    : "=r"(ra[mi][0]),"=r"(ra[mi][1]),"=r"(ra[mi][2]),"=r"(ra[mi][3]) : "r"(ad));
            }
            unsigned rb[4][2];
            #pragma unroll
            for (int h = 0; h < 2; h++){
                unsigned r0,r1,r2,r3;
                if (TRANS_B){
                    unsigned bd = bAddr + (unsigned)((h*16*ASTR + ks*16)*2);
                    asm volatile("ldmatrix.sync.aligned.m8n8.x4.shared.b16 {%0,%1,%2,%3}, [%4];"
                        : "=r"(r0),"=r"(r1),"=r"(r2),"=r"(r3) : "r"(bd));
                } else {
                    unsigned bd = bAddr + (unsigned)((ks*16*BSTR + h*16)*2);
                    asm volatile("ldmatrix.sync.aligned.m8n8.x4.trans.shared.b16 {%0,%1,%2,%3}, [%4];"
                        : "=r"(r0),"=r"(r1),"=r"(r2),"=r"(r3) : "r"(bd));
                }
                rb[h*2][0]=r0; rb[h*2][1]=r1; rb[h*2+1][0]=r2; rb[h*2+1][1]=r3;
            }
            #pragma unroll
            for (int mi = 0; mi < MI; mi++)
                #pragma unroll
                for (int ni = 0; ni < 4; ni++)
                    mma16816(acc[mi][ni], ra[mi], rb[ni]);
        }
        coA += A_ST*2;   if (coA == NSTG*A_ST*2)   coA = 0;
        coB += B_ST_L*2; if (coB == NSTG*B_ST_L*2) coB = 0;
    }

    #pragma unroll
    for (int mi = 0; mi < MI; mi++)
        #pragma unroll
        for (int ni = 0; ni < 4; ni++){
            int c = col0 + wn*32 + ni*8 + t4*2;
            int nv = (c + 1 < N) ? 2 : (c < N ? 1 : 0);
            if (nv){
                int r = row0 + wm*WROWS + mi*16 + gr8;
                if (r < M)     epi(bz, r,     c, acc[mi][ni][0], acc[mi][ni][1], nv);
                if (r + 8 < M) epi(bz, r + 8, c, acc[mi][ni][2], acc[mi][ni][3], nv);
            }
        }
}

// ---------------- epilogues ----------------
struct EpiCat {
    const float* gamma; const float* beta;
    __device__ void operator()(int, int r, int c, float a0, float a1, int nv) {
        if (c < 2*H_){
            float s0 = silu_f(a0 + g_bcat[c]);
            float s1 = silu_f(a1 + g_bcat[c+1]);
            if (c < H_)  st_bf2(&g_v_bf[(size_t)r*H_ + c], s0, s1);
            else         st_bf2(&g_gate_bf[(size_t)r*H_ + c - H_], s0, s1);
        } else {
            int cq = c - 2*H_;
            int s = r % S_;
            float s0 = silu_f(a0 + g_bcat[c]);
            float s1 = silu_f(a1 + g_bcat[c+1]);
            float q0 = fmaf(s0, gamma[cq],        beta[cq]);
            float q1 = fmaf(s1, gamma[cq+1],      beta[cq+1]);
            float k0 = fmaf(s0, gamma[QK_+cq],    beta[QK_+cq]);
            float k1 = fmaf(s1, gamma[QK_+cq+1],  beta[QK_+cq+1]);
            if (cq < 32){
                float2 cs = g_rot[s*16 + (cq>>1)];
                float q0n = q0*cs.x - q1*cs.y, q1n = q1*cs.x + q0*cs.y;
                float k0n = k0*cs.x - k1*cs.y, k1n = k1*cs.x + k0*cs.y;
                q0=q0n; q1=q1n; k0=k0n; k1=k1n;
            }
            size_t base = (size_t)r*QK_;
            st_bf2(&g_q_bf[base+cq], q0, q1);
            st_bf2(&g_k_bf[base+cq], k0, k1);
        }
    }
};
struct EpiScores {
    const float* mask2;
    __device__ void operator()(int bz, int r, int c, float a0, float a1, int nv) {
        size_t rowb = ((size_t)bz*S_ + r)*ATS;
        if (nv == 2){
            float2 mk = *reinterpret_cast<const float2*>(&mask2[r*S_ + c]);
            float v0 = a0 + g_bias[r - c + (S_-1)];
            float v1 = a1 + g_bias[r - c - 1 + (S_-1)];
            float t0 = fmaxf(v0 * (1.0f/S_), 0.f);
            float t1 = fmaxf(v1 * (1.0f/S_), 0.f);
            st_bf2(&g_attn_bf[rowb + c], t0*t0*mk.x, t1*t1*mk.y);
        } else {
            float v0 = a0 + g_bias[r - c + (S_-1)];
            float t0 = fmaxf(v0 * (1.0f/S_), 0.f);
            g_attn_bf[rowb + c] = __float2bfloat16(t0*t0*mask2[r*S_ + c]);
        }
    }
};
struct EpiOut {
    int t2c = -1;
    __device__ __forceinline__ int get_t2(int bz){
        if (t2c < 0){
            int cm = g_cmax[bz];
            int cnt = 0, best = -1;
            #pragma unroll
            for (int t = 16; t >= 1; t--){
                cnt += g_hist2[bz*17 + t];
                if (t <= cm && cnt > 3600 && t > best) best = t;
            }
            t2c = (best >= 0) ? best : cm;
        }
        return t2c;
    }
    __device__ __forceinline__ float gm(int bz, int r, int c, int t2){
        int rr = r % 5, cc = c % 5;
        if (rr == 4 || cc == 4) return 0.0f;
        int cnt = g_counts[bz*12000 + (r/5)*120 + (c/5)];
        return (cnt >= t2) ? 1.0f : 0.25f;
    }
    __device__ void operator()(int bz, int r, int c, float a0, float a1, int nv) {
        int t2 = get_t2(bz);
        size_t idx = ((size_t)bz*S_ + r)*H_ + c;
        if (nv == 2){
            __nv_bfloat162 gt = *reinterpret_cast<const __nv_bfloat162*>(&g_gate_bf[idx]);
            st_bf2(&g_o_bf[idx],
                   gm(bz,r,c,t2)   * a0 * __bfloat162float(gt.x),
                   gm(bz,r,c+1,t2) * a1 * __bfloat162float(gt.y));
        } else {
            g_o_bf[idx] = __float2bfloat16(gm(bz,r,c,t2) * a0 * __bfloat162float(g_gate_bf[idx]));
        }
    }
};
struct EpiFinal {
    const float* bout; const float* x; float* out;
    __device__ void operator()(int, int r, int c, float a0, float a1, int nv) {
        size_t idx = (size_t)r*D_ + c;
        if (nv == 2){
            float2 xv = *reinterpret_cast<const float2*>(&x[idx]);
            *reinterpret_cast<float2*>(&out[idx]) =
                make_float2(a0 + bout[c] + xv.x, a1 + bout[c+1] + xv.y);
        } else {
            out[idx] = a0 + bout[c] + x[idx];
        }
    }
};

// ---------------- gate statistics (bf16 gate) ----------------
__global__ __launch_bounds__(256) void gate_hist_kernel(){
    int b = blockIdx.y;
    __shared__ int sh[129];
    __shared__ unsigned smax;
    int tid = threadIdx.x, lane = tid & 31;
    for (int i = tid; i < 129; i += 256) sh[i] = 0;
    if (tid == 0) smax = 0u;
    __syncthreads();
    const uint4* gp = reinterpret_cast<const uint4*>(g_gate_bf + (size_t)b*S_*H_);
    const int n8 = S_*H_/8;
    int cnt0 = 0;
    unsigned localmax = 0u;
    int stride = gridDim.x * 256;
    for (int i = blockIdx.x*256 + tid; i < n8; i += stride){
        uint4 v = gp[i];
        unsigned words[4] = {v.x, v.y, v.z, v.w};
        #pragma unroll
        for (int wi = 0; wi < 4; wi++){
            __nv_bfloat162 pr = *reinterpret_cast<__nv_bfloat162*>(&words[wi]);
            #pragma unroll
            for (int e = 0; e < 2; e++){
                float gv = __bfloat162float(e ? pr.y : pr.x);
                float a = fabsf(gv);
                int bin = (int)floorf(a); if (bin > 128) bin = 128;
                if (bin == 0) cnt0++;
                else atomicAdd(&sh[bin], 1);
                unsigned u = __float_as_uint(gv);
                u = (u & 0x80000000u) ? ~u : (u | 0x80000000u);
                if (u > localmax) localmax = u;
            }
        }
    }
    #pragma unroll
    for (int o = 16; o; o >>= 1){
        cnt0 += __shfl_xor_sync(0xffffffffu, cnt0, o);
        unsigned om = __shfl_xor_sync(0xffffffffu, localmax, o);
        if (om > localmax) localmax = om;
    }
    if (lane == 0){
        if (cnt0) atomicAdd(&sh[0], cnt0);
        atomicMax(&smax, localmax);
    }
    __syncthreads();
    for (int i = tid; i < 129; i += 256) if (sh[i]) atomicAdd(&g_hist[b*129 + i], sh[i]);
    if (tid == 0) atomicMax(&g_gmax[b], smax);
}

__global__ __launch_bounds__(256) void counts_kernel(){
    int b = blockIdx.y;
    __shared__ int shist[129];
    __shared__ int strim;
    __shared__ int sh2[17];
    __shared__ int scmax;
    int tid = threadIdx.x;
    if (tid < 129) shist[tid] = g_hist[b*129 + tid];
    if (tid < 17)  sh2[tid] = 0;
    if (tid == 0)  scmax = 0;
    __syncthreads();
    if (tid == 0){
        unsigned u = g_gmax[b];
        u = (u & 0x80000000u) ? (u & 0x7FFFFFFFu) : ~u;
        int gmax = (int)floorf(__uint_as_float(u));
        int cnt = 0, best = 0;
        for (int t = 128; t >= 1; t--){
            cnt += shist[t];
            if (t <= gmax && cnt > 90000 && t > best) best = t;
        }
        strim = best < 1 ? 1 : best;
    }
    __syncthreads();
    int idx = blockIdx.x*256 + tid;
    if (idx < 12000){
        int i = idx / 120, j = idx % 120;
        float thr = (float)strim;
        const bf16* gb = g_gate_bf + (size_t)b*S_*H_;
        int cnt = 0;
        #pragma unroll
        for (int r = 0; r < 4; r++)
            #pragma unroll
            for (int c = 0; c < 4; c++)
                cnt += (fabsf(__bfloat162float(gb[(i*5+r)*H_ + j*5+c])) >= thr);
        g_counts[b*12000 + idx] = (unsigned char)cnt;
        atomicMax(&scmax, cnt);
        atomicAdd(&sh2[cnt], 1);
    }
    __syncthreads();
    if (tid < 17 && sh2[tid]) atomicAdd(&g_hist2[b*17 + tid], sh2[tid]);
    if (tid == 0) atomicMax(&g_cmax[b], scmax);
}

// ---------------- launch ----------------
extern "C" void kernel_launch(void* const* d_in, const int* in_sizes, int n_in,
                              void* d_out, int out_size){
    (void)in_sizes; (void)n_in; (void)out_size;
    const float* x       = (const float*)d_in[0];
    const float* mask2   = (const float*)d_in[1];
    const float* ln_g    = (const float*)d_in[2];
    const float* ln_b    = (const float*)d_in[3];
    const float* Wh      = (const float*)d_in[4];
    const float* bh      = (const float*)d_in[5];
    const float* Wqk     = (const float*)d_in[6];
    const float* bqk     = (const float*)d_in[7];
    const float* gamma   = (const float*)d_in[8];
    const float* beta    = (const float*)d_in[9];
    const float* rel_emb = (const float*)d_in[10];
    const float* Wout    = (const float*)d_in[11];
    const float* bout    = (const float*)d_in[12];
    float* out = (float*)d_out;

    bf16 *nx, *q, *k, *v, *attn, *o, *wcat, *wout;
    cudaGetSymbolAddress((void**)&nx,   g_nx_bf);
    cudaGetSymbolAddress((void**)&q,    g_q_bf);
    cudaGetSymbolAddress((void**)&k,    g_k_bf);
    cudaGetSymbolAddress((void**)&v,    g_v_bf);
    cudaGetSymbolAddress((void**)&attn, g_attn_bf);
    cudaGetSymbolAddress((void**)&o,    g_o_bf);
    cudaGetSymbolAddress((void**)&wcat, g_Wcat);
    cudaGetSymbolAddress((void**)&wout, g_Wout_bf);

    const int M = B_*S_;   // 10000

    // merged setup + LayerNorm (independent work)
    setup_ln_kernel<<<SETUP_BLOCKS + LN_BLOCKS, 256>>>(
        rel_emb, Wh, Wqk, Wout, bh, bqk, x, ln_g, ln_b);

    // combined: [h | qk] = silu(nx @ Wcat + bcat), gamma/beta+rotary fused on qk region
    gemm_bf<64,false><<<dim3((NCAT+63)/64, (M+BM-1)/BM, 1), 256>>>(
        nx, wcat, M, NCAT, D_, NXS, NCAT, 0L, 0L, EpiCat{gamma, beta});

    // attn scores (batched NT)
    gemm_bf<64,true><<<dim3((S_+63)/64, (S_+BM-1)/BM, B_), 256>>>(
        q, k, S_, S_, QK_, QK_, QK_, (long)S_*QK_, (long)S_*QK_, EpiScores{mask2});

    gate_hist_kernel<<<dim3(38, B_), 256>>>();
    counts_kernel<<<dim3(47, B_), 256>>>();

    // o = gm * (attn @ v) * gate
    gemm_bf<64,false><<<dim3((H_+63)/64, (S_+BM-1)/BM, B_), 256>>>(
        attn, v, S_, H_, S_, ATS, H_, (long)S_*ATS, (long)S_*H_, EpiOut{});

    // out = o @ Wout + bout + x
    gemm_bf<64,false><<<dim3((D_+63)/64, (M+BM-1)/BM, 1), 256>>>(
        o, wout, M, D_, H_, H_, WOS, 0L, 0L, EpiFinal{bout, x, out});
}

// round 14
// speedup vs baseline: 1.1259x; 1.0015x over previous
#include <cuda_runtime.h>
#include <cuda_bf16.h>
#include <math.h>

#define B_  20
#define S_  500
#define D_  300
#define H_  600
#define QK_ 128
#define NXS 304
#define ATS 512
#define WOS 304
#define NCAT 1328
#define SETUP_BLOCKS ((D_*NCAT + 255)/256)   // 1557
#define LN_BLOCKS (B_*S_/8)                  // 1250

typedef __nv_bfloat16 bf16;

// ---------------- scratch (device globals; no allocation) ----------------
__device__ __align__(16) bf16  g_nx_bf[B_*S_*NXS];
__device__ __align__(16) bf16  g_q_bf[B_*S_*QK_];
__device__ __align__(16) bf16  g_k_bf[B_*S_*QK_];
__device__ __align__(16) bf16  g_v_bf[B_*S_*H_];
__device__ __align__(16) bf16  g_gate_bf[B_*S_*H_];
__device__ __align__(16) bf16  g_attn_bf[(size_t)B_*S_*ATS];
__device__ __align__(16) bf16  g_o_bf[B_*S_*H_];
__device__ __align__(16) bf16  g_Wcat[D_*NCAT];
__device__ float g_bcat[NCAT];
__device__ __align__(16) bf16  g_Wout_bf[H_*WOS];
__device__ float g_bias[1024];
__device__ float2 g_rot[S_*16];
__device__ int   g_hist[B_*129];
__device__ unsigned g_gmax[B_];
__device__ unsigned char g_counts[B_*100*120];
__device__ int   g_cmax[B_];
__device__ int   g_hist2[B_*17];

// ---------------- accurate fp32 exp ----------------
__device__ __forceinline__ float my_expf(float x){
    x = fminf(fmaxf(x, -87.0f), 87.0f);
    float t = fmaf(x, 1.4426950408889634f, 12582912.0f);
    float n = t - 12582912.0f;
    float r = fmaf(n, -0.693359375f, x);
    r = fmaf(n, 2.1219444005469058e-4f, r);
    float p = 1.9841269841e-4f;
    p = fmaf(p, r, 1.3888888889e-3f);
    p = fmaf(p, r, 8.3333333333e-3f);
    p = fmaf(p, r, 4.1666666667e-2f);
    p = fmaf(p, r, 1.6666666667e-1f);
    p = fmaf(p, r, 0.5f);
    p = fmaf(p, r, 1.0f);
    p = fmaf(p, r, 1.0f);
    int e = (int)n;
    return p * __int_as_float((e + 127) << 23);
}
__device__ __forceinline__ float silu_f(float v){
    return v * __fdividef(1.0f, 1.0f + my_expf(-v));
}
__device__ __forceinline__ void st_bf2(bf16* p, float lo, float hi){
    __nv_bfloat162 v;
    v.x = __float2bfloat16(lo);
    v.y = __float2bfloat16(hi);
    *reinterpret_cast<__nv_bfloat162*>(p) = v;
}

// ------------- merged setup + LayerNorm (independent work, one launch) -------------
__global__ __launch_bounds__(256) void setup_ln_kernel(
        const float* __restrict__ rel_emb,
        const float* __restrict__ Wh,
        const float* __restrict__ Wqk,
        const float* __restrict__ Wout,
        const float* __restrict__ bh,
        const float* __restrict__ bqk,
        const float* __restrict__ x,
        const float* __restrict__ lg,
        const float* __restrict__ lb){
    if (blockIdx.x < SETUP_BLOCKS){
        int i = blockIdx.x * 256 + threadIdx.x;
        if (i < B_*129) g_hist[i] = 0;
        if (i < B_*17)  g_hist2[i] = 0;
        if (i < B_)     { g_gmax[i] = 0u; g_cmax[i] = 0; }
        if (i < 999){
            int n = i - (S_-1);
            int ret = (n < 0) ? 16 : 0;
            int na = n < 0 ? -n : n;
            int bucket;
            if (na < 8) bucket = ret + na;
            else {
                float lnum = (float)log((double)na / 8.0);
                float lden = (float)log(16.0);
                float q = (float)((double)lnum / (double)lden);
                int vil = 8 + (int)(q * 8.0f);
                if (vil > 15) vil = 15;
                bucket = ret + vil;
            }
            g_bias[i] = rel_emb[bucket] * sqrtf(128.0f);
        }
        if (i < S_*16){
            int s = i >> 4, f = i & 15;
            double inv = pow(10000.0, -(double)(2*f)/32.0);
            float fr = (float)s * (float)inv;
            g_rot[i] = make_float2((float)cos((double)fr), (float)sin((double)fr));
        }
        if (i < NCAT) g_bcat[i] = (i < 2*H_) ? bh[i] : bqk[i - 2*H_];
        if (i < D_*NCAT){
            int row = i / NCAT, col = i % NCAT;
            float w = (col < 2*H_) ? Wh[row*(2*H_) + col] : Wqk[row*QK_ + (col - 2*H_)];
            g_Wcat[i] = __float2bfloat16(w);
        }
        if (i < H_*D_){
            int row = i / D_, col = i % D_;
            g_Wout_bf[row*WOS + col] = __float2bfloat16(Wout[i]);
        }
    } else {
        // LayerNorm: warp-per-row, 8 rows per block
        int w = threadIdx.x >> 5, lane = threadIdx.x & 31;
        int bs = (blockIdx.x - SETUP_BLOCKS) * 8 + w;
        int batch = bs / S_, s = bs % S_;
        const float* xr = x + (size_t)bs * D_;
        float xv[10];
        float sum = 0.f, ss = 0.f;
        #pragma unroll
        for (int j = 0; j < 10; j++){
            int i = j*32 + lane;
            float v = (i < D_) ? xr[i] : 0.f;
            xv[j] = v; sum += v; ss = fmaf(v, v, ss);
        }
        #pragma unroll
        for (int o = 16; o; o >>= 1){
            sum += __shfl_xor_sync(0xffffffffu, sum, o);
            ss  += __shfl_xor_sync(0xffffffffu, ss,  o);
        }
        float mean = sum * (1.0f / D_);
        float var  = ss * (1.0f / D_) - mean*mean;
        float inv  = rsqrtf(var + 1e-5f);
        size_t selfRow = (size_t)bs * NXS;
        size_t nextRow = ((size_t)batch*S_ + s + 1) * NXS;
        #pragma unroll
        for (int j = 0; j < 10; j++){
            int i = j*32 + lane;
            if (i >= D_) break;
            float val = (xv[j]-mean)*inv*lg[i] + lb[i];
            if (i < D_/2){
                if (s+1 < S_) g_nx_bf[nextRow + i] = __float2bfloat16(val);
            } else {
                g_nx_bf[selfRow + i] = __float2bfloat16(val);
            }
        }
        if (s == 0){
            #pragma unroll
            for (int j = 0; j < 5; j++){
                int i = j*32 + lane;
                if (i < D_/2) g_nx_bf[selfRow + i] = __float2bfloat16(0.f);
            }
        }
    }
}

// ===== bf16 mma.sync GEMM: BM=128, BN templated, 3-stage cp.async.cg =====
#define BM 128
#define BK 32
#define ASTR 40
#define A_ST (BM*ASTR)
#define NSTG 3

__device__ __forceinline__ void mma16816(float c[4], const unsigned a[4], const unsigned b[2]){
    asm volatile("mma.sync.aligned.m16n8k16.row.col.f32.bf16.bf16.f32 "
                 "{%0,%1,%2,%3}, {%4,%5,%6,%7}, {%8,%9}, {%0,%1,%2,%3};"
                 : "+f"(c[0]), "+f"(c[1]), "+f"(c[2]), "+f"(c[3])
                 : "r"(a[0]), "r"(a[1]), "r"(a[2]), "r"(a[3]), "r"(b[0]), "r"(b[1]));
}
__device__ __forceinline__ void cp16(unsigned dst, const void* src, int bytes){
    asm volatile("cp.async.cg.shared.global [%0], [%1], 16, %2;" :: "r"(dst), "l"(src), "r"(bytes));
}
__device__ __forceinline__ void cp_commit(){ asm volatile("cp.async.commit_group;"); }
__device__ __forceinline__ void cp_wait1(){ asm volatile("cp.async.wait_group 1;"); }
__device__ __forceinline__ int clampb(int rem){ return rem < 0 ? 0 : (rem > 16 ? 16 : rem); }

template<int BN_, bool TRANS_B, class Epi>
__global__ __launch_bounds__(256) void gemm_bf(const bf16* __restrict__ A,
        const bf16* __restrict__ Bm, int M, int N, int K, int lda, int ldb,
        long sA, long sB, Epi epi)
{
    constexpr int WN_CNT = BN_/32;
    constexpr int WM_CNT = 8/WN_CNT;
    constexpr int WROWS  = BM/WM_CNT;
    constexpr int MI     = WROWS/16;
    constexpr int BSTR   = TRANS_B ? ASTR : (BN_ + 8);
    constexpr int B_ST_L = TRANS_B ? BN_*ASTR : BK*BSTR;

    __shared__ bf16 smA[NSTG][A_ST];
    __shared__ bf16 smB[NSTG][B_ST_L];

    int bz = blockIdx.z;
    A  += (size_t)bz * sA;
    Bm += (size_t)bz * sB;
    int row0 = blockIdx.y*BM, col0 = blockIdx.x*BN_;
    int tid = threadIdx.x, warp = tid>>5, lane = tid&31;
    int wm = warp / WN_CNT, wn = warp % WN_CNT;
    int gr8 = lane>>2, t4 = lane&3;

    unsigned aS = (unsigned)__cvta_generic_to_shared(&smA[0][0]);
    unsigned bS = (unsigned)__cvta_generic_to_shared(&smB[0][0]);

    int ar = tid>>2;
    int ak = (tid&3)*8;
    bool vA0 = (row0 + ar)      < M;
    bool vA1 = (row0 + ar + 64) < M;
    const bf16* pA0 = A + (size_t)(row0 + ar)      * lda + ak;
    const bf16* pA1 = A + (size_t)(row0 + ar + 64) * lda + ak;
    unsigned dA0 = aS + (unsigned)((ar*ASTR + ak)*2);
    unsigned dA1 = dA0 + (unsigned)(64*ASTR*2);

    bool vB0 = true, vB1 = true;
    const bf16* pB0 = Bm; const bf16* pB1 = Bm;
    unsigned dB0 = bS, dB1 = bS;
    int constNB = 0;
    int bk8 = 0, brow = 0;
    if (TRANS_B){
        if (BN_ == 128){
            brow = tid>>2; bk8 = (tid&3)*8;
            vB0 = (col0 + brow)      < N;
            vB1 = (col0 + brow + 64) < N;
            pB0 = Bm + (size_t)(col0 + brow)      * ldb + bk8;
            pB1 = Bm + (size_t)(col0 + brow + 64) * ldb + bk8;
            dB0 = bS + (unsigned)((brow*ASTR + bk8)*2);
            dB1 = dB0 + (unsigned)(64*ASTR*2);
        } else {
            brow = tid>>2; bk8 = (tid&3)*8;
            vB0 = (col0 + brow) < N;
            pB0 = Bm + (size_t)(col0 + brow) * ldb + bk8;
            dB0 = bS + (unsigned)((brow*ASTR + bk8)*2);
        }
    } else {
        if (BN_ == 128){
            brow = tid>>4;
            int bc8 = (tid&15)*8;
            int gn = col0 + bc8;
            constNB = clampb((N - gn)*2);
            pB0 = Bm + (size_t)brow * ldb + gn;
            pB1 = pB0 + (size_t)16 * ldb;
            dB0 = bS + (unsigned)((brow*BSTR + bc8)*2);
            dB1 = dB0 + (unsigned)(16*BSTR*2);
        } else {
            brow = tid>>3;
            int bc8 = (tid&7)*8;
            int gn = col0 + bc8;
            constNB = clampb((N - gn)*2);
            pB0 = Bm + (size_t)brow * ldb + gn;
            dB0 = bS + (unsigned)((brow*BSTR + bc8)*2);
        }
    }

    auto load_stage = [&](unsigned soA, unsigned soB, int kk){
        int bytes0 = vA0 ? clampb((K - (kk + ak))*2) : 0;
        int bytes1 = vA1 ? clampb((K - (kk + ak))*2) : 0;
        cp16(dA0 + soA, bytes0 ? (const void*)pA0 : (const void*)A, bytes0);
        cp16(dA1 + soA, bytes1 ? (const void*)pA1 : (const void*)A, bytes1);
        pA0 += BK; pA1 += BK;
        if (TRANS_B){
            int kb = clampb((K - (kk + bk8))*2);
            int b0 = vB0 ? kb : 0;
            cp16(dB0 + soB, b0 ? (const void*)pB0 : (const void*)Bm, b0);
            pB0 += BK;
            if (BN_ == 128){
                int b1 = vB1 ? kb : 0;
                cp16(dB1 + soB, b1 ? (const void*)pB1 : (const void*)Bm, b1);
                pB1 += BK;
            }
        } else {
            int b0 = ((kk + brow) < K) ? constNB : 0;
            cp16(dB0 + soB, b0 ? (const void*)pB0 : (const void*)Bm, b0);
            pB0 += (size_t)BK * ldb;
            if (BN_ == 128){
                int b1 = ((kk + brow + 16) < K) ? constNB : 0;
                cp16(dB1 + soB, b1 ? (const void*)pB1 : (const void*)Bm, b1);
                pB1 += (size_t)BK * ldb;
            }
        }
    };

    unsigned aAddrBase = aS + (unsigned)(((wm*WROWS + (lane&15))*ASTR + (lane>>4)*8)*2);
    unsigned bAddrBase;
    {
        int m = lane>>3, i = lane&7;
        if (TRANS_B){
            int rowoff = i + ((m>>1)<<3);
            int kcoff  = (m&1)<<3;
            bAddrBase = bS + (unsigned)(((wn*32 + rowoff)*ASTR + kcoff)*2);
        } else {
            int krow = i + ((m&1)<<3);
            int ncoff = (m>>1)<<3;
            bAddrBase = bS + (unsigned)((krow*BSTR + wn*32 + ncoff)*2);
        }
    }

    float acc[MI][4][4] = {};

    int nk = (K + BK - 1)/BK;
    load_stage(0, 0, 0);                 cp_commit();
    load_stage(A_ST*2, B_ST_L*2, BK);    cp_commit();

    unsigned poA = 2*A_ST*2, poB = 2*B_ST_L*2;
    unsigned coA = 0,        coB = 0;

    for (int it = 0; it < nk; it++){
        cp_wait1();
        __syncthreads();
        if (it + 2 < nk) load_stage(poA, poB, (it+2)*BK);
        cp_commit();
        poA += A_ST*2;   if (poA == NSTG*A_ST*2)   poA = 0;
        poB += B_ST_L*2; if (poB == NSTG*B_ST_L*2) poB = 0;

        unsigned aAddr = aAddrBase + coA;
        unsigned bAddr = bAddrBase + coB;
        #pragma unroll
        for (int ks = 0; ks < 2; ks++){
            unsigned ra[MI][4];
            #pragma unroll
            for (int mi = 0; mi < MI; mi++){
                unsigned ad = aAddr + (unsigned)((mi*16*ASTR + ks*16)*2);
                asm volatile("ldmatrix.sync.aligned.m8n8.x4.shared.b16 {%0,%1,%2,%3}, [%4];"
                    : "=r"(ra[mi][0]),"=r"(ra[mi][1]),"=r"(ra[mi][2]),"=r"(ra[mi][3]) : "r"(ad));
            }
            unsigned rb[4][2];
            #pragma unroll
            for (int h = 0; h < 2; h++){
                unsigned r0,r1,r2,r3;
                if (TRANS_B){
                    unsigned bd = bAddr + (unsigned)((h*16*ASTR + ks*16)*2);
                    asm volatile("ldmatrix.sync.aligned.m8n8.x4.shared.b16 {%0,%1,%2,%3}, [%4];"
                        : "=r"(r0),"=r"(r1),"=r"(r2),"=r"(r3) : "r"(bd));
                } else {
                    unsigned bd = bAddr + (unsigned)((ks*16*BSTR + h*16)*2);
                    asm volatile("ldmatrix.sync.aligned.m8n8.x4.trans.shared.b16 {%0,%1,%2,%3}, [%4];"
                        : "=r"(r0),"=r"(r1),"=r"(r2),"=r"(r3) : "r"(bd));
                }
                rb[h*2][0]=r0; rb[h*2][1]=r1; rb[h*2+1][0]=r2; rb[h*2+1][1]=r3;
            }
            #pragma unroll
            for (int mi = 0; mi < MI; mi++)
                #pragma unroll
                for (int ni = 0; ni < 4; ni++)
                    mma16816(acc[mi][ni], ra[mi], rb[ni]);
        }
        coA += A_ST*2;   if (coA == NSTG*A_ST*2)   coA = 0;
        coB += B_ST_L*2; if (coB == NSTG*B_ST_L*2) coB = 0;
    }

    #pragma unroll
    for (int mi = 0; mi < MI; mi++)
        #pragma unroll
        for (int ni = 0; ni < 4; ni++){
            int c = col0 + wn*32 + ni*8 + t4*2;
            int nv = (c + 1 < N) ? 2 : (c < N ? 1 : 0);
            if (nv){
                int r = row0 + wm*WROWS + mi*16 + gr8;
                if (r < M)     epi(bz, r,     c, acc[mi][ni][0], acc[mi][ni][1], nv);
                if (r + 8 < M) epi(bz, r + 8, c, acc[mi][ni][2], acc[mi][ni][3], nv);
            }
        }
}

// ---------------- epilogues ----------------
struct EpiCat {
    const float* gamma; const float* beta;
    __device__ void operator()(int, int r, int c, float a0, float a1, int nv) {
        if (c < 2*H_){
            float s0 = silu_f(a0 + g_bcat[c]);
            float s1 = silu_f(a1 + g_bcat[c+1]);
            if (c < H_)  st_bf2(&g_v_bf[(size_t)r*H_ + c], s0, s1);
            else         st_bf2(&g_gate_bf[(size_t)r*H_ + c - H_], s0, s1);
        } else {
            int cq = c - 2*H_;
            int s = r % S_;
            float s0 = silu_f(a0 + g_bcat[c]);
            float s1 = silu_f(a1 + g_bcat[c+1]);
            float q0 = fmaf(s0, gamma[cq],        beta[cq]);
            float q1 = fmaf(s1, gamma[cq+1],      beta[cq+1]);
            float k0 = fmaf(s0, gamma[QK_+cq],    beta[QK_+cq]);
            float k1 = fmaf(s1, gamma[QK_+cq+1],  beta[QK_+cq+1]);
            if (cq < 32){
                float2 cs = g_rot[s*16 + (cq>>1)];
                float q0n = q0*cs.x - q1*cs.y, q1n = q1*cs.x + q0*cs.y;
                float k0n = k0*cs.x - k1*cs.y, k1n = k1*cs.x + k0*cs.y;
                q0=q0n; q1=q1n; k0=k0n; k1=k1n;
            }
            size_t base = (size_t)r*QK_;
            st_bf2(&g_q_bf[base+cq], q0, q1);
            st_bf2(&g_k_bf[base+cq], k0, k1);
        }
    }
};
struct EpiScores {
    const float* mask2;
    __device__ void operator()(int bz, int r, int c, float a0, float a1, int nv) {
        size_t rowb = ((size_t)bz*S_ + r)*ATS;
        if (nv == 2){
            float2 mk = *reinterpret_cast<const float2*>(&mask2[r*S_ + c]);
            float v0 = a0 + g_bias[r - c + (S_-1)];
            float v1 = a1 + g_bias[r - c - 1 + (S_-1)];
            float t0 = fmaxf(v0 * (1.0f/S_), 0.f);
            float t1 = fmaxf(v1 * (1.0f/S_), 0.f);
            st_bf2(&g_attn_bf[rowb + c], t0*t0*mk.x, t1*t1*mk.y);
        } else {
            float v0 = a0 + g_bias[r - c + (S_-1)];
            float t0 = fmaxf(v0 * (1.0f/S_), 0.f);
            g_attn_bf[rowb + c] = __float2bfloat16(t0*t0*mask2[r*S_ + c]);
        }
    }
};
struct EpiOut {
    int t2c = -1;
    __device__ __forceinline__ int get_t2(int bz){
        if (t2c < 0){
            int cm = g_cmax[bz];
            int cnt = 0, best = -1;
            #pragma unroll
            for (int t = 16; t >= 1; t--){
                cnt += g_hist2[bz*17 + t];
                if (t <= cm && cnt > 3600 && t > best) best = t;
            }
            t2c = (best >= 0) ? best : cm;
        }
        return t2c;
    }
    __device__ __forceinline__ float gm(int bz, int r, int c, int t2){
        int rr = r % 5, cc = c % 5;
        if (rr == 4 || cc == 4) return 0.0f;
        int cnt = g_counts[bz*12000 + (r/5)*120 + (c/5)];
        return (cnt >= t2) ? 1.0f : 0.25f;
    }
    __device__ void operator()(int bz, int r, int c, float a0, float a1, int nv) {
        int t2 = get_t2(bz);
        size_t idx = ((size_t)bz*S_ + r)*H_ + c;
        if (nv == 2){
            __nv_bfloat162 gt = *reinterpret_cast<const __nv_bfloat162*>(&g_gate_bf[idx]);
            st_bf2(&g_o_bf[idx],
                   gm(bz,r,c,t2)   * a0 * __bfloat162float(gt.x),
                   gm(bz,r,c+1,t2) * a1 * __bfloat162float(gt.y));
        } else {
            g_o_bf[idx] = __float2bfloat16(gm(bz,r,c,t2) * a0 * __bfloat162float(g_gate_bf[idx]));
        }
    }
};
struct EpiFinal {
    const float* bout; const float* x; float* out;
    __device__ void operator()(int, int r, int c, float a0, float a1, int nv) {
        size_t idx = (size_t)r*D_ + c;
        if (nv == 2){
            float2 xv = *reinterpret_cast<const float2*>(&x[idx]);
            *reinterpret_cast<float2*>(&out[idx]) =
                make_float2(a0 + bout[c] + xv.x, a1 + bout[c+1] + xv.y);
        } else {
            out[idx] = a0 + bout[c] + x[idx];
        }
    }
};

// ------- gate statistics: hist only for |g|>=1 (hist[0] is dead), hmax2 max -------
__global__ __launch_bounds__(256) void gate_hist_kernel(){
    int b = blockIdx.y;
    __shared__ int sh[129];
    __shared__ unsigned smax;
    int tid = threadIdx.x, lane = tid & 31;
    for (int i = tid; i < 129; i += 256) sh[i] = 0;
    if (tid == 0) smax = 0u;
    __syncthreads();
    const uint4* gp = reinterpret_cast<const uint4*>(g_gate_bf + (size_t)b*S_*H_);
    const int n8 = S_*H_/8;
    __nv_bfloat162 vmax = __float2bfloat162_rn(-3.0e38f);
    int stride = gridDim.x * 256;
    for (int i = blockIdx.x*256 + tid; i < n8; i += stride){
        uint4 v = gp[i];
        unsigned words[4] = {v.x, v.y, v.z, v.w};
        #pragma unroll
        for (int wi = 0; wi < 4; wi++){
            __nv_bfloat162 pr = *reinterpret_cast<__nv_bfloat162*>(&words[wi]);
            vmax = __hmax2(vmax, pr);
            unsigned absw = words[wi] & 0x7FFF7FFFu;
            if (__vcmpgeu2(absw, 0x3F803F80u)){            // rare: some |g| >= 1
                float a0 = fabsf(__bfloat162float(pr.x));
                float a1 = fabsf(__bfloat162float(pr.y));
                if (a0 >= 1.f){ int bin = (int)floorf(a0); if (bin > 128) bin = 128; atomicAdd(&sh[bin], 1); }
                if (a1 >= 1.f){ int bin = (int)floorf(a1); if (bin > 128) bin = 128; atomicAdd(&sh[bin], 1); }
            }
        }
    }
    float fm = fmaxf(__bfloat162float(vmax.x), __bfloat162float(vmax.y));
    #pragma unroll
    for (int o = 16; o; o >>= 1)
        fm = fmaxf(fm, __shfl_xor_sync(0xffffffffu, fm, o));
    if (lane == 0){
        unsigned u = __float_as_uint(fm);
        u = (u & 0x80000000u) ? ~u : (u | 0x80000000u);
        atomicMax(&smax, u);
    }
    __syncthreads();
    for (int i = tid; i < 129; i += 256) if (sh[i]) atomicAdd(&g_hist[b*129 + i], sh[i]);
    if (tid == 0) atomicMax(&g_gmax[b], smax);
}

__global__ __launch_bounds__(256) void counts_kernel(){
    int b = blockIdx.y;
    __shared__ int shist[129];
    __shared__ int strim;
    __shared__ int sh2[17];
    __shared__ int scmax;
    int tid = threadIdx.x;
    if (tid < 129) shist[tid] = g_hist[b*129 + tid];
    if (tid < 17)  sh2[tid] = 0;
    if (tid == 0)  scmax = 0;
    __syncthreads();
    if (tid == 0){
        unsigned u = g_gmax[b];
        u = (u & 0x80000000u) ? (u & 0x7FFFFFFFu) : ~u;
        int gmax = (int)floorf(__uint_as_float(u));
        int cnt = 0, best = 0;
        for (int t = 128; t >= 1; t--){
            cnt += shist[t];
            if (t <= gmax && cnt > 90000 && t > best) best = t;
        }
        strim = best < 1 ? 1 : best;
    }
    __syncthreads();
    int idx = blockIdx.x*256 + tid;
    if (idx < 12000){
        int i = idx / 120, j = idx % 120;
        float thr = (float)strim;
        const bf16* gb = g_gate_bf + (size_t)b*S_*H_;
        int cnt = 0;
        #pragma unroll
        for (int r = 0; r < 4; r++)
            #pragma unroll
            for (int c = 0; c < 4; c++)
                cnt += (fabsf(__bfloat162float(gb[(i*5+r)*H_ + j*5+c])) >= thr);
        g_counts[b*12000 + idx] = (unsigned char)cnt;
        atomicMax(&scmax, cnt);
        atomicAdd(&sh2[cnt], 1);
    }
    __syncthreads();
    if (tid < 17 && sh2[tid]) atomicAdd(&g_hist2[b*17 + tid], sh2[tid]);
    if (tid == 0) atomicMax(&g_cmax[b], scmax);
}

// ---------------- launch ----------------
extern "C" void kernel_launch(void* const* d_in, const int* in_sizes, int n_in,
                              void* d_out, int out_size){
    (void)in_sizes; (void)n_in; (void)out_size;
    const float* x       = (const float*)d_in[0];
    const float* mask2   = (const float*)d_in[1];
    const float* ln_g    = (const float*)d_in[2];
    const float* ln_b    = (const float*)d_in[3];
    const float* Wh      = (const float*)d_in[4];
    const float* bh      = (const float*)d_in[5];
    const float* Wqk     = (const float*)d_in[6];
    const float* bqk     = (const float*)d_in[7];
    const float* gamma   = (const float*)d_in[8];
    const float* beta    = (const float*)d_in[9];
    const float* rel_emb = (const float*)d_in[10];
    const float* Wout    = (const float*)d_in[11];
    const float* bout    = (const float*)d_in[12];
    float* out = (float*)d_out;

    bf16 *nx, *q, *k, *v, *attn, *o, *wcat, *wout;
    cudaGetSymbolAddress((void**)&nx,   g_nx_bf);
    cudaGetSymbolAddress((void**)&q,    g_q_bf);
    cudaGetSymbolAddress((void**)&k,    g_k_bf);
    cudaGetSymbolAddress((void**)&v,    g_v_bf);
    cudaGetSymbolAddress((void**)&attn, g_attn_bf);
    cudaGetSymbolAddress((void**)&o,    g_o_bf);
    cudaGetSymbolAddress((void**)&wcat, g_Wcat);
    cudaGetSymbolAddress((void**)&wout, g_Wout_bf);

    const int M = B_*S_;   // 10000

    setup_ln_kernel<<<SETUP_BLOCKS + LN_BLOCKS, 256>>>(
        rel_emb, Wh, Wqk, Wout, bh, bqk, x, ln_g, ln_b);

    // combined: [h | qk] = silu(nx @ Wcat + bcat), gamma/beta+rotary fused on qk region
    gemm_bf<64,false><<<dim3((NCAT+63)/64, (M+BM-1)/BM, 1), 256>>>(
        nx, wcat, M, NCAT, D_, NXS, NCAT, 0L, 0L, EpiCat{gamma, beta});

    // attn scores (batched NT)
    gemm_bf<64,true><<<dim3((S_+63)/64, (S_+BM-1)/BM, B_), 256>>>(
        q, k, S_, S_, QK_, QK_, QK_, (long)S_*QK_, (long)S_*QK_, EpiScores{mask2});

    gate_hist_kernel<<<dim3(38, B_), 256>>>();
    counts_kernel<<<dim3(47, B_), 256>>>();

    // o = gm * (attn @ v) * gate
    gemm_bf<64,false><<<dim3((H_+63)/64, (S_+BM-1)/BM, B_), 256>>>(
        attn, v, S_, H_, S_, ATS, H_, (long)S_*ATS, (long)S_*H_, EpiOut{});

    // out = o @ Wout + bout + x
    gemm_bf<64,false><<<dim3((D_+63)/64, (M+BM-1)/BM, 1), 256>>>(
        o, wout, M, D_, H_, H_, WOS, 0L, 0L, EpiFinal{bout, x, out});
}

// round 15
// speedup vs baseline: 1.1546x; 1.0255x over previous
#include <cuda_runtime.h>
#include <cuda_bf16.h>
#include <math.h>

#define B_  20
#define S_  500
#define D_  300
#define H_  600
#define QK_ 128
#define NXS 304
#define ATS 512
#define WOS 304
#define NCAT 1328
#define SETUP_BLOCKS ((D_*NCAT + 255)/256)   // 1557
#define LN_BLOCKS (B_*S_/8)                  // 1250

typedef __nv_bfloat16 bf16;

// ---------------- scratch (device globals; no allocation) ----------------
__device__ __align__(16) bf16  g_nx_bf[B_*S_*NXS];
__device__ __align__(16) bf16  g_q_bf[B_*S_*QK_];
__device__ __align__(16) bf16  g_k_bf[B_*S_*QK_];
__device__ __align__(16) bf16  g_v_bf[B_*S_*H_];
__device__ __align__(16) bf16  g_gate_bf[B_*S_*H_];
__device__ __align__(16) bf16  g_attn_bf[(size_t)B_*S_*ATS];
__device__ __align__(16) bf16  g_o_bf[B_*S_*H_];
__device__ __align__(16) bf16  g_Wcat[D_*NCAT];
__device__ float g_bcat[NCAT];
__device__ __align__(16) bf16  g_Wout_bf[H_*WOS];
__device__ float g_bias[1024];
__device__ float2 g_rot[S_*16];
__device__ int   g_hist[B_*129];
__device__ unsigned g_gmax[B_];
__device__ unsigned char g_counts[B_*100*120];
__device__ int   g_cmax[B_];
__device__ int   g_hist2[B_*17];

// ---------------- silu via HW tanh: silu(v) = v * (0.5 + 0.5*tanh(v/2)) ----------------
__device__ __forceinline__ float silu_f(float v){
    float t;
    asm("tanh.approx.f32 %0, %1;" : "=f"(t) : "f"(v * 0.5f));
    return v * fmaf(0.5f, t, 0.5f);
}
__device__ __forceinline__ void st_bf2(bf16* p, float lo, float hi){
    __nv_bfloat162 v;
    v.x = __float2bfloat16(lo);
    v.y = __float2bfloat16(hi);
    *reinterpret_cast<__nv_bfloat162*>(p) = v;
}

// ------------- merged setup + LayerNorm (independent work, one launch) -------------
__global__ __launch_bounds__(256) void setup_ln_kernel(
        const float* __restrict__ rel_emb,
        const float* __restrict__ Wh,
        const float* __restrict__ Wqk,
        const float* __restrict__ Wout,
        const float* __restrict__ bh,
        const float* __restrict__ bqk,
        const float* __restrict__ x,
        const float* __restrict__ lg,
        const float* __restrict__ lb){
    if (blockIdx.x < SETUP_BLOCKS){
        int i = blockIdx.x * 256 + threadIdx.x;
        if (i < B_*129) g_hist[i] = 0;
        if (i < B_*17)  g_hist2[i] = 0;
        if (i < B_)     { g_gmax[i] = 0u; g_cmax[i] = 0; }
        if (i < 999){
            int n = i - (S_-1);
            int ret = (n < 0) ? 16 : 0;
            int na = n < 0 ? -n : n;
            int bucket;
            if (na < 8) bucket = ret + na;
            else {
                float lnum = (float)log((double)na / 8.0);
                float lden = (float)log(16.0);
                float q = (float)((double)lnum / (double)lden);
                int vil = 8 + (int)(q * 8.0f);
                if (vil > 15) vil = 15;
                bucket = ret + vil;
            }
            g_bias[i] = rel_emb[bucket] * sqrtf(128.0f);
        }
        if (i < S_*16){
            int s = i >> 4, f = i & 15;
            double inv = pow(10000.0, -(double)(2*f)/32.0);
            float fr = (float)s * (float)inv;
            g_rot[i] = make_float2((float)cos((double)fr), (float)sin((double)fr));
        }
        if (i < NCAT) g_bcat[i] = (i < 2*H_) ? bh[i] : bqk[i - 2*H_];
        if (i < D_*NCAT){
            int row = i / NCAT, col = i % NCAT;
            float w = (col < 2*H_) ? Wh[row*(2*H_) + col] : Wqk[row*QK_ + (col - 2*H_)];
            g_Wcat[i] = __float2bfloat16(w);
        }
        if (i < H_*D_){
            int row = i / D_, col = i % D_;
            g_Wout_bf[row*WOS + col] = __float2bfloat16(Wout[i]);
        }
    } else {
        int w = threadIdx.x >> 5, lane = threadIdx.x & 31;
        int bs = (blockIdx.x - SETUP_BLOCKS) * 8 + w;
        int batch = bs / S_, s = bs % S_;
        const float* xr = x + (size_t)bs * D_;
        float xv[10];
        float sum = 0.f, ss = 0.f;
        #pragma unroll
        for (int j = 0; j < 10; j++){
            int i = j*32 + lane;
            float v = (i < D_) ? xr[i] : 0.f;
            xv[j] = v; sum += v; ss = fmaf(v, v, ss);
        }
        #pragma unroll
        for (int o = 16; o; o >>= 1){
            sum += __shfl_xor_sync(0xffffffffu, sum, o);
            ss  += __shfl_xor_sync(0xffffffffu, ss,  o);
        }
        float mean = sum * (1.0f / D_);
        float var  = ss * (1.0f / D_) - mean*mean;
        float inv  = rsqrtf(var + 1e-5f);
        size_t selfRow = (size_t)bs * NXS;
        size_t nextRow = ((size_t)batch*S_ + s + 1) * NXS;
        #pragma unroll
        for (int j = 0; j < 10; j++){
            int i = j*32 + lane;
            if (i >= D_) break;
            float val = (xv[j]-mean)*inv*lg[i] + lb[i];
            if (i < D_/2){
                if (s+1 < S_) g_nx_bf[nextRow + i] = __float2bfloat16(val);
            } else {
                g_nx_bf[selfRow + i] = __float2bfloat16(val);
            }
        }
        if (s == 0){
            #pragma unroll
            for (int j = 0; j < 5; j++){
                int i = j*32 + lane;
                if (i < D_/2) g_nx_bf[selfRow + i] = __float2bfloat16(0.f);
            }
        }
    }
}

// ===== bf16 mma.sync GEMM: BM=128, BN templated, 3-stage cp.async.cg =====
#define BM 128
#define BK 32
#define ASTR 40
#define A_ST (BM*ASTR)
#define NSTG 3

__device__ __forceinline__ void mma16816(float c[4], const unsigned a[4], const unsigned b[2]){
    asm volatile("mma.sync.aligned.m16n8k16.row.col.f32.bf16.bf16.f32 "
                 "{%0,%1,%2,%3}, {%4,%5,%6,%7}, {%8,%9}, {%0,%1,%2,%3};"
                 : "+f"(c[0]), "+f"(c[1]), "+f"(c[2]), "+f"(c[3])
                 : "r"(a[0]), "r"(a[1]), "r"(a[2]), "r"(a[3]), "r"(b[0]), "r"(b[1]));
}
__device__ __forceinline__ void cp16(unsigned dst, const void* src, int bytes){
    asm volatile("cp.async.cg.shared.global [%0], [%1], 16, %2;" :: "r"(dst), "l"(src), "r"(bytes));
}
__device__ __forceinline__ void cp_commit(){ asm volatile("cp.async.commit_group;"); }
__device__ __forceinline__ void cp_wait1(){ asm volatile("cp.async.wait_group 1;"); }
__device__ __forceinline__ int clampb(int rem){ return rem < 0 ? 0 : (rem > 16 ? 16 : rem); }

template<int BN_, bool TRANS_B, class Epi>
__global__ __launch_bounds__(256) void gemm_bf(const bf16* __restrict__ A,
        const bf16* __restrict__ Bm, int M, int N, int K, int lda, int ldb,
        long sA, long sB, Epi epi)
{
    constexpr int WN_CNT = BN_/32;
    constexpr int WM_CNT = 8/WN_CNT;
    constexpr int WROWS  = BM/WM_CNT;
    constexpr int MI     = WROWS/16;
    constexpr int BSTR   = TRANS_B ? ASTR : (BN_ + 8);
    constexpr int B_ST_L = TRANS_B ? BN_*ASTR : BK*BSTR;

    __shared__ bf16 smA[NSTG][A_ST];
    __shared__ bf16 smB[NSTG][B_ST_L];

    int bz = blockIdx.z;
    A  += (size_t)bz * sA;
    Bm += (size_t)bz * sB;
    int row0 = blockIdx.y*BM, col0 = blockIdx.x*BN_;
    int tid = threadIdx.x, warp = tid>>5, lane = tid&31;
    int wm = warp / WN_CNT, wn = warp % WN_CNT;
    int gr8 = lane>>2, t4 = lane&3;

    unsigned aS = (unsigned)__cvta_generic_to_shared(&smA[0][0]);
    unsigned bS = (unsigned)__cvta_generic_to_shared(&smB[0][0]);

    int ar = tid>>2;
    int ak = (tid&3)*8;
    bool vA0 = (row0 + ar)      < M;
    bool vA1 = (row0 + ar + 64) < M;
    const bf16* pA0 = A + (size_t)(row0 + ar)      * lda + ak;
    const bf16* pA1 = A + (size_t)(row0 + ar + 64) * lda + ak;
    unsigned dA0 = aS + (unsigned)((ar*ASTR + ak)*2);
    unsigned dA1 = dA0 + (unsigned)(64*ASTR*2);

    bool vB0 = true, vB1 = true;
    const bf16* pB0 = Bm; const bf16* pB1 = Bm;
    unsigned dB0 = bS, dB1 = bS;
    int constNB = 0;
    int bk8 = 0, brow = 0;
    if (TRANS_B){
        if (BN_ == 128){
            brow = tid>>2; bk8 = (tid&3)*8;
            vB0 = (col0 + brow)      < N;
            vB1 = (col0 + brow + 64) < N;
            pB0 = Bm + (size_t)(col0 + brow)      * ldb + bk8;
            pB1 = Bm + (size_t)(col0 + brow + 64) * ldb + bk8;
            dB0 = bS + (unsigned)((brow*ASTR + bk8)*2);
            dB1 = dB0 + (unsigned)(64*ASTR*2);
        } else {
            brow = tid>>2; bk8 = (tid&3)*8;
            vB0 = (col0 + brow) < N;
            pB0 = Bm + (size_t)(col0 + brow) * ldb + bk8;
            dB0 = bS + (unsigned)((brow*ASTR + bk8)*2);
        }
    } else {
        if (BN_ == 128){
            brow = tid>>4;
            int bc8 = (tid&15)*8;
            int gn = col0 + bc8;
            constNB = clampb((N - gn)*2);
            pB0 = Bm + (size_t)brow * ldb + gn;
            pB1 = pB0 + (size_t)16 * ldb;
            dB0 = bS + (unsigned)((brow*BSTR + bc8)*2);
            dB1 = dB0 + (unsigned)(16*BSTR*2);
        } else {
            brow = tid>>3;
            int bc8 = (tid&7)*8;
            int gn = col0 + bc8;
            constNB = clampb((N - gn)*2);
            pB0 = Bm + (size_t)brow * ldb + gn;
            dB0 = bS + (unsigned)((brow*BSTR + bc8)*2);
        }
    }

    auto load_stage = [&](unsigned soA, unsigned soB, int kk){
        int bytes0 = vA0 ? clampb((K - (kk + ak))*2) : 0;
        int bytes1 = vA1 ? clampb((K - (kk + ak))*2) : 0;
        cp16(dA0 + soA, bytes0 ? (const void*)pA0 : (const void*)A, bytes0);
        cp16(dA1 + soA, bytes1 ? (const void*)pA1 : (const void*)A, bytes1);
        pA0 += BK; pA1 += BK;
        if (TRANS_B){
            int kb = clampb((K - (kk + bk8))*2);
            int b0 = vB0 ? kb : 0;
            cp16(dB0 + soB, b0 ? (const void*)pB0 : (const void*)Bm, b0);
            pB0 += BK;
            if (BN_ == 128){
                int b1 = vB1 ? kb : 0;
                cp16(dB1 + soB, b1 ? (const void*)pB1 : (const void*)Bm, b1);
                pB1 += BK;
            }
        } else {
            int b0 = ((kk + brow) < K) ? constNB : 0;
            cp16(dB0 + soB, b0 ? (const void*)pB0 : (const void*)Bm, b0);
            pB0 += (size_t)BK * ldb;
            if (BN_ == 128){
                int b1 = ((kk + brow + 16) < K) ? constNB : 0;
                cp16(dB1 + soB, b1 ? (const void*)pB1 : (const void*)Bm, b1);
                pB1 += (size_t)BK * ldb;
            }
        }
    };

    unsigned aAddrBase = aS + (unsigned)(((wm*WROWS + (lane&15))*ASTR + (lane>>4)*8)*2);
    unsigned bAddrBase;
    {
        int m = lane>>3, i = lane&7;
        if (TRANS_B){
            int rowoff = i + ((m>>1)<<3);
            int kcoff  = (m&1)<<3;
            bAddrBase = bS + (unsigned)(((wn*32 + rowoff)*ASTR + kcoff)*2);
        } else {
            int krow = i + ((m&1)<<3);
            int ncoff = (m>>1)<<3;
            bAddrBase = bS + (unsigned)((krow*BSTR + wn*32 + ncoff)*2);
        }
    }

    float acc[MI][4][4] = {};

    int nk = (K + BK - 1)/BK;
    load_stage(0, 0, 0);                 cp_commit();
    load_stage(A_ST*2, B_ST_L*2, BK);    cp_commit();

    unsigned poA = 2*A_ST*2, poB = 2*B_ST_L*2;
    unsigned coA = 0,        coB = 0;

    for (int it = 0; it < nk; it++){
        cp_wait1();
        __syncthreads();
        if (it + 2 < nk) load_stage(poA, poB, (it+2)*BK);
        cp_commit();
        poA += A_ST*2;   if (poA == NSTG*A_ST*2)   poA = 0;
        poB += B_ST_L*2; if (poB == NSTG*B_ST_L*2) poB = 0;

        unsigned aAddr = aAddrBase + coA;
        unsigned bAddr = bAddrBase + coB;
        #pragma unroll
        for (int ks = 0; ks < 2; ks++){
            unsigned ra[MI][4];
            #pragma unroll
            for (int mi = 0; mi < MI; mi++){
                unsigned ad = aAddr + (unsigned)((mi*16*ASTR + ks*16)*2);
                asm volatile("ldmatrix.sync.aligned.m8n8.x4.shared.b16 {%0,%1,%2,%3}, [%4];"
                    : "=r"(ra[mi][0]),"=r"(ra[mi][1]),"=r"(ra[mi][2]),"=r"(ra[mi][3]) : "r"(ad));
            }
            unsigned rb[4][2];
            #pragma unroll
            for (int h = 0; h < 2; h++){
                unsigned r0,r1,r2,r3;
                if (TRANS_B){
                    unsigned bd = bAddr + (unsigned)((h*16*ASTR + ks*16)*2);
                    asm volatile("ldmatrix.sync.aligned.m8n8.x4.shared.b16 {%0,%1,%2,%3}, [%4];"
                        : "=r"(r0),"=r"(r1),"=r"(r2),"=r"(r3) : "r"(bd));
                } else {
                    unsigned bd = bAddr + (unsigned)((ks*16*BSTR + h*16)*2);
                    asm volatile("ldmatrix.sync.aligned.m8n8.x4.trans.shared.b16 {%0,%1,%2,%3}, [%4];"
                        : "=r"(r0),"=r"(r1),"=r"(r2),"=r"(r3) : "r"(bd));
                }
                rb[h*2][0]=r0; rb[h*2][1]=r1; rb[h*2+1][0]=r2; rb[h*2+1][1]=r3;
            }
            #pragma unroll
            for (int mi = 0; mi < MI; mi++)
                #pragma unroll
                for (int ni = 0; ni < 4; ni++)
                    mma16816(acc[mi][ni], ra[mi], rb[ni]);
        }
        coA += A_ST*2;   if (coA == NSTG*A_ST*2)   coA = 0;
        coB += B_ST_L*2; if (coB == NSTG*B_ST_L*2) coB = 0;
    }

    #pragma unroll
    for (int mi = 0; mi < MI; mi++)
        #pragma unroll
        for (int ni = 0; ni < 4; ni++){
            int c = col0 + wn*32 + ni*8 + t4*2;
            int nv = (c + 1 < N) ? 2 : (c < N ? 1 : 0);
            if (nv){
                int r = row0 + wm*WROWS + mi*16 + gr8;
                if (r < M)     epi(bz, r,     c, acc[mi][ni][0], acc[mi][ni][1], nv);
                if (r + 8 < M) epi(bz, r + 8, c, acc[mi][ni][2], acc[mi][ni][3], nv);
            }
        }
}

// ---------------- epilogues ----------------
struct EpiCat {
    const float* gamma; const float* beta;
    __device__ void operator()(int, int r, int c, float a0, float a1, int nv) {
        if (c < 2*H_){
            float s0 = silu_f(a0 + g_bcat[c]);
            float s1 = silu_f(a1 + g_bcat[c+1]);
            if (c < H_)  st_bf2(&g_v_bf[(size_t)r*H_ + c], s0, s1);
            else         st_bf2(&g_gate_bf[(size_t)r*H_ + c - H_], s0, s1);
        } else {
            int cq = c - 2*H_;
            int s = r % S_;
            float s0 = silu_f(a0 + g_bcat[c]);
            float s1 = silu_f(a1 + g_bcat[c+1]);
            float q0 = fmaf(s0, gamma[cq],        beta[cq]);
            float q1 = fmaf(s1, gamma[cq+1],      beta[cq+1]);
            float k0 = fmaf(s0, gamma[QK_+cq],    beta[QK_+cq]);
            float k1 = fmaf(s1, gamma[QK_+cq+1],  beta[QK_+cq+1]);
            if (cq < 32){
                float2 cs = g_rot[s*16 + (cq>>1)];
                float q0n = q0*cs.x - q1*cs.y, q1n = q1*cs.x + q0*cs.y;
                float k0n = k0*cs.x - k1*cs.y, k1n = k1*cs.x + k0*cs.y;
                q0=q0n; q1=q1n; k0=k0n; k1=k1n;
            }
            size_t base = (size_t)r*QK_;
            st_bf2(&g_q_bf[base+cq], q0, q1);
            st_bf2(&g_k_bf[base+cq], k0, k1);
        }
    }
};
struct EpiScores {
    const float* mask2;
    __device__ void operator()(int bz, int r, int c, float a0, float a1, int nv) {
        size_t rowb = ((size_t)bz*S_ + r)*ATS;
        if (nv == 2){
            float2 mk = *reinterpret_cast<const float2*>(&mask2[r*S_ + c]);
            float v0 = a0 + g_bias[r - c + (S_-1)];
            float v1 = a1 + g_bias[r - c - 1 + (S_-1)];
            float t0 = fmaxf(v0 * (1.0f/S_), 0.f);
            float t1 = fmaxf(v1 * (1.0f/S_), 0.f);
            st_bf2(&g_attn_bf[rowb + c], t0*t0*mk.x, t1*t1*mk.y);
        } else {
            float v0 = a0 + g_bias[r - c + (S_-1)];
            float t0 = fmaxf(v0 * (1.0f/S_), 0.f);
            g_attn_bf[rowb + c] = __float2bfloat16(t0*t0*mask2[r*S_ + c]);
        }
    }
};
struct EpiOut {
    int t2c = -1;
    __device__ __forceinline__ int get_t2(int bz){
        if (t2c < 0){
            int cm = g_cmax[bz];
            int cnt = 0, best = -1;
            #pragma unroll
            for (int t = 16; t >= 1; t--){
                cnt += g_hist2[bz*17 + t];
                if (t <= cm && cnt > 3600 && t > best) best = t;
            }
            t2c = (best >= 0) ? best : cm;
        }
        return t2c;
    }
    __device__ __forceinline__ float gm(int bz, int r, int c, int t2){
        int rr = r % 5, cc = c % 5;
        if (rr == 4 || cc == 4) return 0.0f;
        int cnt = g_counts[bz*12000 + (r/5)*120 + (c/5)];
        return (cnt >= t2) ? 1.0f : 0.25f;
    }
    __device__ void operator()(int bz, int r, int c, float a0, float a1, int nv) {
        int t2 = get_t2(bz);
        size_t idx = ((size_t)bz*S_ + r)*H_ + c;
        if (nv == 2){
            __nv_bfloat162 gt = *reinterpret_cast<const __nv_bfloat162*>(&g_gate_bf[idx]);
            st_bf2(&g_o_bf[idx],
                   gm(bz,r,c,t2)   * a0 * __bfloat162float(gt.x),
                   gm(bz,r,c+1,t2) * a1 * __bfloat162float(gt.y));
        } else {
            g_o_bf[idx] = __float2bfloat16(gm(bz,r,c,t2) * a0 * __bfloat162float(g_gate_bf[idx]));
        }
    }
};
struct EpiFinal {
    const float* bout; const float* x; float* out;
    __device__ void operator()(int, int r, int c, float a0, float a1, int nv) {
        size_t idx = (size_t)r*D_ + c;
        if (nv == 2){
            float2 xv = *reinterpret_cast<const float2*>(&x[idx]);
            *reinterpret_cast<float2*>(&out[idx]) =
                make_float2(a0 + bout[c] + xv.x, a1 + bout[c+1] + xv.y);
        } else {
            out[idx] = a0 + bout[c] + x[idx];
        }
    }
};

// ------- gate statistics: hist only for |g|>=1 (hist[0] dead), hmax2 max -------
__global__ __launch_bounds__(256) void gate_hist_kernel(){
    int b = blockIdx.y;
    __shared__ int sh[129];
    __shared__ unsigned smax;
    int tid = threadIdx.x, lane = tid & 31;
    for (int i = tid; i < 129; i += 256) sh[i] = 0;
    if (tid == 0) smax = 0u;
    __syncthreads();
    const uint4* gp = reinterpret_cast<const uint4*>(g_gate_bf + (size_t)b*S_*H_);
    const int n8 = S_*H_/8;
    __nv_bfloat162 vmax = __float2bfloat162_rn(-3.0e38f);
    int stride = gridDim.x * 256;
    for (int i = blockIdx.x*256 + tid; i < n8; i += stride){
        uint4 v = gp[i];
        unsigned words[4] = {v.x, v.y, v.z, v.w};
        #pragma unroll
        for (int wi = 0; wi < 4; wi++){
            __nv_bfloat162 pr = *reinterpret_cast<__nv_bfloat162*>(&words[wi]);
            vmax = __hmax2(vmax, pr);
            unsigned absw = words[wi] & 0x7FFF7FFFu;
            if (__vcmpgeu2(absw, 0x3F803F80u)){
                float a0 = fabsf(__bfloat162float(pr.x));
                float a1 = fabsf(__bfloat162float(pr.y));
                if (a0 >= 1.f){ int bin = (int)floorf(a0); if (bin > 128) bin = 128; atomicAdd(&sh[bin], 1); }
                if (a1 >= 1.f){ int bin = (int)floorf(a1); if (bin > 128) bin = 128; atomicAdd(&sh[bin], 1); }
            }
        }
    }
    float fm = fmaxf(__bfloat162float(vmax.x), __bfloat162float(vmax.y));
    #pragma unroll
    for (int o = 16; o; o >>= 1)
        fm = fmaxf(fm, __shfl_xor_sync(0xffffffffu, fm, o));
    if (lane == 0){
        unsigned u = __float_as_uint(fm);
        u = (u & 0x80000000u) ? ~u : (u | 0x80000000u);
        atomicMax(&smax, u);
    }
    __syncthreads();
    for (int i = tid; i < 129; i += 256) if (sh[i]) atomicAdd(&g_hist[b*129 + i], sh[i]);
    if (tid == 0) atomicMax(&g_gmax[b], smax);
}

__global__ __launch_bounds__(256) void counts_kernel(){
    int b = blockIdx.y;
    __shared__ int shist[129];
    __shared__ int strim;
    __shared__ int sh2[17];
    __shared__ int scmax;
    int tid = threadIdx.x;
    if (tid < 129) shist[tid] = g_hist[b*129 + tid];
    if (tid < 17)  sh2[tid] = 0;
    if (tid == 0)  scmax = 0;
    __syncthreads();
    if (tid == 0){
        unsigned u = g_gmax[b];
        u = (u & 0x80000000u) ? (u & 0x7FFFFFFFu) : ~u;
        int gmax = (int)floorf(__uint_as_float(u));
        int cnt = 0, best = 0;
        for (int t = 128; t >= 1; t--){
            cnt += shist[t];
            if (t <= gmax && cnt > 90000 && t > best) best = t;
        }
        strim = best < 1 ? 1 : best;
    }
    __syncthreads();
    int idx = blockIdx.x*256 + tid;
    if (idx < 12000){
        int i = idx / 120, j = idx % 120;
        float thr = (float)strim;
        const bf16* gb = g_gate_bf + (size_t)b*S_*H_;
        int cnt = 0;
        #pragma unroll
        for (int r = 0; r < 4; r++)
            #pragma unroll
            for (int c = 0; c < 4; c++)
                cnt += (fabsf(__bfloat162float(gb[(i*5+r)*H_ + j*5+c])) >= thr);
        g_counts[b*12000 + idx] = (unsigned char)cnt;
        atomicMax(&scmax, cnt);
        atomicAdd(&sh2[cnt], 1);
    }
    __syncthreads();
    if (tid < 17 && sh2[tid]) atomicAdd(&g_hist2[b*17 + tid], sh2[tid]);
    if (tid == 0) atomicMax(&g_cmax[b], scmax);
}

// ---------------- launch ----------------
extern "C" void kernel_launch(void* const* d_in, const int* in_sizes, int n_in,
                              void* d_out, int out_size){
    (void)in_sizes; (void)n_in; (void)out_size;
    const float* x       = (const float*)d_in[0];
    const float* mask2   = (const float*)d_in[1];
    const float* ln_g    = (const float*)d_in[2];
    const float* ln_b    = (const float*)d_in[3];
    const float* Wh      = (const float*)d_in[4];
    const float* bh      = (const float*)d_in[5];
    const float* Wqk     = (const float*)d_in[6];
    const float* bqk     = (const float*)d_in[7];
    const float* gamma   = (const float*)d_in[8];
    const float* beta    = (const float*)d_in[9];
    const float* rel_emb = (const float*)d_in[10];
    const float* Wout    = (const float*)d_in[11];
    const float* bout    = (const float*)d_in[12];
    float* out = (float*)d_out;

    bf16 *nx, *q, *k, *v, *attn, *o, *wcat, *wout;
    cudaGetSymbolAddress((void**)&nx,   g_nx_bf);
    cudaGetSymbolAddress((void**)&q,    g_q_bf);
    cudaGetSymbolAddress((void**)&k,    g_k_bf);
    cudaGetSymbolAddress((void**)&v,    g_v_bf);
    cudaGetSymbolAddress((void**)&attn, g_attn_bf);
    cudaGetSymbolAddress((void**)&o,    g_o_bf);
    cudaGetSymbolAddress((void**)&wcat, g_Wcat);
    cudaGetSymbolAddress((void**)&wout, g_Wout_bf);

    const int M = B_*S_;   // 10000

    setup_ln_kernel<<<SETUP_BLOCKS + LN_BLOCKS, 256>>>(
        rel_emb, Wh, Wqk, Wout, bh, bqk, x, ln_g, ln_b);

    // combined: [h | qk] = silu(nx @ Wcat + bcat), gamma/beta+rotary fused on qk region
    gemm_bf<64,false><<<dim3((NCAT+63)/64, (M+BM-1)/BM, 1), 256>>>(
        nx, wcat, M, NCAT, D_, NXS, NCAT, 0L, 0L, EpiCat{gamma, beta});

    // attn scores (batched NT)
    gemm_bf<64,true><<<dim3((S_+63)/64, (S_+BM-1)/BM, B_), 256>>>(
        q, k, S_, S_, QK_, QK_, QK_, (long)S_*QK_, (long)S_*QK_, EpiScores{mask2});

    gate_hist_kernel<<<dim3(38, B_), 256>>>();
    counts_kernel<<<dim3(47, B_), 256>>>();

    // o = gm * (attn @ v) * gate
    gemm_bf<64,false><<<dim3((H_+63)/64, (S_+BM-1)/BM, B_), 256>>>(
        attn, v, S_, H_, S_, ATS, H_, (long)S_*ATS, (long)S_*H_, EpiOut{});

    // out = o @ Wout + bout + x
    gemm_bf<64,false><<<dim3((D_+63)/64, (M+BM-1)/BM, 1), 256>>>(
        o, wout, M, D_, H_, H_, WOS, 0L, 0L, EpiFinal{bout, x, out});
}